// round 10
// baseline (speedup 1.0000x reference)
#include <cuda_runtime.h>
#include <cuda_bf16.h>
#include <cuda_fp16.h>
#include <math.h>
#include <stdint.h>

#define N_NODES 1024
#define N_EDGES 32768
#define DIM     1024
#define HEADS   8
#define DH      128
#define KPROJ   256
#define QKV_N   1152   // w_to_q (1024) ++ w_to_k (128), fused GEMM

// ---------------------------------------------------------------------------
// Scratch (device globals -- no allocation allowed)
// ---------------------------------------------------------------------------
__device__ __half        g_e16[N_EDGES * DIM];                         // edge fp16
__device__ __half        g_weT16[DIM * DIM];                           // w_edge^T fp16
__device__ __nv_bfloat16 g_nh[N_NODES * DIM],  g_nl[N_NODES * DIM];    // node hi/lo
__device__ __nv_bfloat16 g_wqT_h[DIM * DIM],   g_wqT_l[DIM * DIM];     // w_query^T
__device__ __nv_bfloat16 g_wqkT_h[QKV_N * DIM], g_wqkT_l[QKV_N * DIM]; // [w_to_q|w_to_k]^T
__device__ __nv_bfloat16 g_woT_h[DIM * DIM],   g_woT_l[DIM * DIM];     // w_out^T
__device__ __nv_bfloat16 g_xqh[N_NODES * DIM], g_xql[N_NODES * DIM];   // xq hi/lo
__device__ float         g_qkv[N_NODES * QKV_N];                       // [q | kv] fp32
__device__ float         g_kproj[KPROJ * DH];
__device__ __nv_bfloat16 g_ah[N_NODES * DIM],  g_al[N_NODES * DIM];    // attn out hi/lo
__device__ float         g_xattn[N_NODES * DIM];

// ---------------------------------------------------------------------------
// Generic-ISA PTX helpers
// ---------------------------------------------------------------------------
__device__ __forceinline__ uint32_t smem_u32(const void* p) {
    uint32_t a;
    asm("{ .reg .u64 t; cvta.to.shared.u64 t, %1; cvt.u32.u64 %0, t; }"
        : "=r"(a) : "l"(p));
    return a;
}

#define CP_ASYNC16(dst, src) \
    asm volatile("cp.async.cg.shared.global [%0], [%1], 16;" :: "r"(dst), "l"(src))
#define CP_COMMIT() asm volatile("cp.async.commit_group;" ::: "memory")
#define CP_WAIT1()  asm volatile("cp.async.wait_group 1;" ::: "memory")

#define LDSM4(r, addr) \
    asm volatile("ldmatrix.sync.aligned.m8n8.x4.shared.b16 {%0,%1,%2,%3}, [%4];" \
        : "=r"((r)[0]), "=r"((r)[1]), "=r"((r)[2]), "=r"((r)[3]) : "r"(addr))

__device__ __forceinline__ void mma16816(float* c, const uint32_t* a, const uint32_t* b) {
    asm volatile(
        "mma.sync.aligned.m16n8k16.row.col.f32.bf16.bf16.f32 "
        "{%0,%1,%2,%3}, {%4,%5,%6,%7}, {%8,%9}, {%0,%1,%2,%3};"
        : "+f"(c[0]), "+f"(c[1]), "+f"(c[2]), "+f"(c[3])
        : "r"(a[0]), "r"(a[1]), "r"(a[2]), "r"(a[3]), "r"(b[0]), "r"(b[1]));
}

__device__ __forceinline__ void mma16816h(float* c, const uint32_t* a, const uint32_t* b) {
    asm volatile(
        "mma.sync.aligned.m16n8k16.row.col.f32.f16.f16.f32 "
        "{%0,%1,%2,%3}, {%4,%5,%6,%7}, {%8,%9}, {%0,%1,%2,%3};"
        : "+f"(c[0]), "+f"(c[1]), "+f"(c[2]), "+f"(c[3])
        : "r"(a[0]), "r"(a[1]), "r"(a[2]), "r"(a[3]), "r"(b[0]), "r"(b[1]));
}

#define GK 1024

// ===========================================================================
// EDGE GEMM (fp16, 1-term, SW128 swizzle) -- unchanged (at legacy-HMMA ceiling)
// ===========================================================================
#define E_NTK 16
#define E_TILE 16384
#define E_STAGE (2 * E_TILE)
#define E_SM (512 + 3 * E_STAGE)

__global__ void __launch_bounds__(256, 2) gemm_f16_sw(
    const __half* __restrict__ A16, const __half* __restrict__ BhT,
    const float* __restrict__ bias, float* __restrict__ Cf, int Nt)
{
    extern __shared__ char smem[];
    const uint32_t sb = smem_u32(smem);
    const int tid = threadIdx.x;
    const int wid = tid >> 5;
    const int lane = tid & 31;
    const int bm = blockIdx.y * 128;
    const int bn = blockIdx.x * 128;

    if (tid < 128) ((float*)smem)[tid] = bias ? bias[bn + tid] : 0.f;

    const __half* srcA = A16 + (size_t)bm * GK;
    const __half* srcB = BhT + (size_t)bn * GK;

    auto load_stage = [&](int kt, int s) {
        const uint32_t base = sb + 512 + s * E_STAGE;
#pragma unroll
        for (int i = 0; i < 4; i++) {
            const int idx = i * 256 + tid;
            const int row = idx >> 3, c = idx & 7;
            const uint32_t sw = (uint32_t)row * 128 + (uint32_t)((c ^ (row & 7)) << 4);
            CP_ASYNC16(base + sw, srcA + (size_t)row * GK + kt * 64 + c * 8);
        }
#pragma unroll
        for (int i = 0; i < 4; i++) {
            const int idx = i * 256 + tid;
            const int row = idx >> 3, c = idx & 7;
            const uint32_t sw = (uint32_t)row * 128 + (uint32_t)((c ^ (row & 7)) << 4);
            CP_ASYNC16(base + E_TILE + sw, srcB + (size_t)row * GK + kt * 64 + c * 8);
        }
    };

    load_stage(0, 0); CP_COMMIT();
    load_stage(1, 1); CP_COMMIT();

    const int wm = (wid >> 2) * 64;
    const int wn = (wid & 3) * 32;
    const int l7 = lane & 7;
    const int brow_off = l7 + ((lane >> 4) << 3);

    float acc[4][4][4];
#pragma unroll
    for (int mt = 0; mt < 4; mt++)
#pragma unroll
        for (int nt = 0; nt < 4; nt++)
#pragma unroll
            for (int j = 0; j < 4; j++) acc[mt][nt][j] = 0.f;

    for (int kt = 0; kt < E_NTK; kt++) {
        CP_WAIT1();
        __syncthreads();

        if (kt + 2 < E_NTK) { load_stage(kt + 2, (kt + 2) % 3); CP_COMMIT(); }

        const uint32_t st = sb + 512 + (kt % 3) * E_STAGE;
        const uint32_t aRow = st + (uint32_t)(wm + (lane & 15)) * 128;
        const uint32_t bRowBase = st + E_TILE + (uint32_t)(wn + brow_off) * 128;

#pragma unroll
        for (int kh = 0; kh < 4; kh++) {
            const uint32_t aChunk = (uint32_t)(((kh << 1) | (lane >> 4)) ^ l7) << 4;
            const uint32_t bChunk = (uint32_t)(((kh << 1) | ((lane >> 3) & 1)) ^ l7) << 4;
            uint32_t aF[4][4], bF[2][4];
#pragma unroll
            for (int p = 0; p < 2; p++)
                LDSM4(bF[p], bRowBase + (uint32_t)(p * 16) * 128 + bChunk);
#pragma unroll
            for (int mt = 0; mt < 4; mt++)
                LDSM4(aF[mt], aRow + (uint32_t)(mt * 16) * 128 + aChunk);
#pragma unroll
            for (int mt = 0; mt < 4; mt++)
#pragma unroll
                for (int nt = 0; nt < 4; nt++)
                    mma16816h(acc[mt][nt], aF[mt], &bF[nt >> 1][(nt & 1) * 2]);
        }
    }

    const float* bs = (const float*)smem;
#pragma unroll
    for (int mt = 0; mt < 4; mt++) {
#pragma unroll
        for (int nt = 0; nt < 4; nt++) {
            const int c = wn + nt * 8 + (lane & 3) * 2;
            const size_t r0 = (size_t)bm + wm + mt * 16 + (lane >> 2);
            *(float2*)&Cf[r0 * Nt + bn + c] =
                make_float2(acc[mt][nt][0] + bs[c], acc[mt][nt][1] + bs[c + 1]);
            *(float2*)&Cf[(r0 + 8) * Nt + bn + c] =
                make_float2(acc[mt][nt][2] + bs[c], acc[mt][nt][3] + bs[c + 1]);
        }
    }
}

// ===========================================================================
// NODE GEMM (bf16 3-term, SW128 swizzle) -- unchanged
// ===========================================================================
#define N_NTK 16
#define N_ATILE 8192
#define N_BTILE 16384
#define N_STAGE (2 * N_ATILE + 2 * N_BTILE)
#define N_SM (512 + 3 * N_STAGE)

__global__ void __launch_bounds__(256, 1) gemm_bf16_sw(
    const __nv_bfloat16* __restrict__ Ah, const __nv_bfloat16* __restrict__ Al,
    const __nv_bfloat16* __restrict__ BhT, const __nv_bfloat16* __restrict__ BlT,
    const float* __restrict__ bias,
    float* __restrict__ Cf, __nv_bfloat16* __restrict__ Ch, __nv_bfloat16* __restrict__ Cl,
    int Nt)
{
    extern __shared__ char smem[];
    const uint32_t sb = smem_u32(smem);
    const int tid = threadIdx.x;
    const int wid = tid >> 5;
    const int lane = tid & 31;
    const int bm = blockIdx.y * 64;
    const int bn = blockIdx.x * 128;

    if (tid < 128) ((float*)smem)[tid] = bias ? bias[bn + tid] : 0.f;

    const __nv_bfloat16* sAh = Ah + (size_t)bm * GK;
    const __nv_bfloat16* sAl = Al + (size_t)bm * GK;
    const __nv_bfloat16* sBh = BhT + (size_t)bn * GK;
    const __nv_bfloat16* sBl = BlT + (size_t)bn * GK;

    auto load_stage = [&](int kt, int s) {
        const uint32_t base = sb + 512 + s * N_STAGE;
#pragma unroll
        for (int i = 0; i < 2; i++) {
            const int idx = i * 256 + tid;
            const int row = idx >> 3, c = idx & 7;
            const uint32_t sw = (uint32_t)row * 128 + (uint32_t)((c ^ (row & 7)) << 4);
            CP_ASYNC16(base + sw, sAh + (size_t)row * GK + kt * 64 + c * 8);
            CP_ASYNC16(base + N_ATILE + sw, sAl + (size_t)row * GK + kt * 64 + c * 8);
        }
#pragma unroll
        for (int i = 0; i < 4; i++) {
            const int idx = i * 256 + tid;
            const int row = idx >> 3, c = idx & 7;
            const uint32_t sw = (uint32_t)row * 128 + (uint32_t)((c ^ (row & 7)) << 4);
            CP_ASYNC16(base + 2 * N_ATILE + sw, sBh + (size_t)row * GK + kt * 64 + c * 8);
            CP_ASYNC16(base + 2 * N_ATILE + N_BTILE + sw,
                       sBl + (size_t)row * GK + kt * 64 + c * 8);
        }
    };

    load_stage(0, 0); CP_COMMIT();
    load_stage(1, 1); CP_COMMIT();

    const int wm = (wid >> 2) * 32;
    const int wn = (wid & 3) * 32;
    const int l7 = lane & 7;
    const int brow_off = l7 + ((lane >> 4) << 3);

    float acc[2][4][4];
#pragma unroll
    for (int mt = 0; mt < 2; mt++)
#pragma unroll
        for (int nt = 0; nt < 4; nt++)
#pragma unroll
            for (int j = 0; j < 4; j++) acc[mt][nt][j] = 0.f;

    for (int kt = 0; kt < N_NTK; kt++) {
        CP_WAIT1();
        __syncthreads();

        if (kt + 2 < N_NTK) { load_stage(kt + 2, (kt + 2) % 3); CP_COMMIT(); }

        const uint32_t st = sb + 512 + (kt % 3) * N_STAGE;
        const uint32_t ahRow = st + (uint32_t)(wm + (lane & 15)) * 128;
        const uint32_t alRow = ahRow + N_ATILE;
        const uint32_t bhRowBase = st + 2 * N_ATILE + (uint32_t)(wn + brow_off) * 128;
        const uint32_t blRowBase = bhRowBase + N_BTILE;

#pragma unroll
        for (int kh = 0; kh < 4; kh++) {
            const uint32_t aChunk = (uint32_t)(((kh << 1) | (lane >> 4)) ^ l7) << 4;
            const uint32_t bChunk = (uint32_t)(((kh << 1) | ((lane >> 3) & 1)) ^ l7) << 4;
            uint32_t aH[2][4], aL[2][4], bHF[2][4], bLF[2][4];
#pragma unroll
            for (int p = 0; p < 2; p++) {
                LDSM4(bHF[p], bhRowBase + (uint32_t)(p * 16) * 128 + bChunk);
                LDSM4(bLF[p], blRowBase + (uint32_t)(p * 16) * 128 + bChunk);
            }
#pragma unroll
            for (int mt = 0; mt < 2; mt++) {
                LDSM4(aH[mt], ahRow + (uint32_t)(mt * 16) * 128 + aChunk);
                LDSM4(aL[mt], alRow + (uint32_t)(mt * 16) * 128 + aChunk);
            }
#pragma unroll
            for (int mt = 0; mt < 2; mt++)
#pragma unroll
                for (int nt = 0; nt < 4; nt++) {
                    const uint32_t* bh = &bHF[nt >> 1][(nt & 1) * 2];
                    const uint32_t* bl = &bLF[nt >> 1][(nt & 1) * 2];
                    mma16816(acc[mt][nt], aH[mt], bh);
                    mma16816(acc[mt][nt], aH[mt], bl);
                    mma16816(acc[mt][nt], aL[mt], bh);
                }
        }
    }

    const float* bs = (const float*)smem;
#pragma unroll
    for (int mt = 0; mt < 2; mt++) {
#pragma unroll
        for (int nt = 0; nt < 4; nt++) {
            const int c = wn + nt * 8 + (lane & 3) * 2;
            const size_t r0 = (size_t)bm + wm + mt * 16 + (lane >> 2);
            const float v0 = acc[mt][nt][0] + bs[c];
            const float v1 = acc[mt][nt][1] + bs[c + 1];
            const float v2 = acc[mt][nt][2] + bs[c];
            const float v3 = acc[mt][nt][3] + bs[c + 1];
            if (Cf) {
                *(float2*)&Cf[r0 * Nt + bn + c]       = make_float2(v0, v1);
                *(float2*)&Cf[(r0 + 8) * Nt + bn + c] = make_float2(v2, v3);
            }
            if (Ch) {
                __nv_bfloat16 h0 = __float2bfloat16(v0), h1 = __float2bfloat16(v1);
                __nv_bfloat16 h2 = __float2bfloat16(v2), h3 = __float2bfloat16(v3);
                *(__nv_bfloat162*)&Ch[r0 * Nt + bn + c] = __halves2bfloat162(h0, h1);
                *(__nv_bfloat162*)&Ch[(r0 + 8) * Nt + bn + c] = __halves2bfloat162(h2, h3);
                *(__nv_bfloat162*)&Cl[r0 * Nt + bn + c] = __halves2bfloat162(
                    __float2bfloat16(v0 - __bfloat162float(h0)),
                    __float2bfloat16(v1 - __bfloat162float(h1)));
                *(__nv_bfloat162*)&Cl[(r0 + 8) * Nt + bn + c] = __halves2bfloat162(
                    __float2bfloat16(v2 - __bfloat162float(h2)),
                    __float2bfloat16(v3 - __bfloat162float(h3)));
            }
        }
    }
}

// ---------------------------------------------------------------------------
// Edge convert: fp32 -> fp16
// ---------------------------------------------------------------------------
#define EDGE_F4 (N_EDGES * DIM / 4)
#define NODE_F4 (N_NODES * DIM / 4)

__global__ void __launch_bounds__(256) conv_edge_kernel(
    const float4* __restrict__ edge, __half2* __restrict__ e16)
{
    const int i = blockIdx.x * 256 + threadIdx.x;
    float4 v = edge[i];
    e16[2 * i + 0] = __halves2half2(__float2half(v.x), __float2half(v.y));
    e16[2 * i + 1] = __halves2half2(__float2half(v.z), __float2half(v.w));
}

// ---------------------------------------------------------------------------
// Node split: fp32 -> bf16 hi/lo
// ---------------------------------------------------------------------------
__global__ void __launch_bounds__(256) split_node_kernel(
    const float4* __restrict__ node, __nv_bfloat162* __restrict__ nh,
    __nv_bfloat162* __restrict__ nl)
{
    const int i = blockIdx.x * 256 + threadIdx.x;
    float4 v = node[i];
    __nv_bfloat16 h0 = __float2bfloat16(v.x), h1 = __float2bfloat16(v.y);
    __nv_bfloat16 h2 = __float2bfloat16(v.z), h3 = __float2bfloat16(v.w);
    nh[2 * i + 0] = __halves2bfloat162(h0, h1);
    nh[2 * i + 1] = __halves2bfloat162(h2, h3);
    nl[2 * i + 0] = __halves2bfloat162(
        __float2bfloat16(v.x - __bfloat162float(h0)),
        __float2bfloat16(v.y - __bfloat162float(h1)));
    nl[2 * i + 1] = __halves2bfloat162(
        __float2bfloat16(v.z - __bfloat162float(h2)),
        __float2bfloat16(v.w - __bfloat162float(h3)));
}

// ---------------------------------------------------------------------------
// Edge weight prep: w_edge[K,N] fp32 -> weT16[N,1024] fp16 transpose
// ---------------------------------------------------------------------------
__global__ void __launch_bounds__(256) wprep_edge_kernel(
    const float* __restrict__ w, __half* __restrict__ oh)
{
    __shared__ float t[32][33];
    const int n0 = (blockIdx.x & 31) * 32, k0 = (blockIdx.x >> 5) * 32;
    const int tx = threadIdx.x, ty = threadIdx.y;
#pragma unroll
    for (int i = 0; i < 4; i++)
        t[ty + i * 8][tx] = w[(size_t)(k0 + ty + i * 8) * 1024 + n0 + tx];
    __syncthreads();
#pragma unroll
    for (int i = 0; i < 4; i++) {
        const int n = n0 + ty + i * 8, k = k0 + tx;
        oh[(size_t)n * 1024 + k] = __float2half(t[tx][ty + i * 8]);
    }
}

// ---------------------------------------------------------------------------
// Node weight prep: 4 transpose+split jobs (w_query, w_to_q, w_to_k, w_out)
// ---------------------------------------------------------------------------
#define WPREP_NODE_BLOCKS (1024 * 3 + 128)

__global__ void __launch_bounds__(256) wprep_node_kernel(
    const float* __restrict__ w_query, const float* __restrict__ w_to_q,
    const float* __restrict__ w_to_k, const float* __restrict__ w_out,
    __nv_bfloat16* __restrict__ wqTh, __nv_bfloat16* __restrict__ wqTl,
    __nv_bfloat16* __restrict__ wqkTh, __nv_bfloat16* __restrict__ wqkTl,
    __nv_bfloat16* __restrict__ woTh, __nv_bfloat16* __restrict__ woTl)
{
    __shared__ float t[32][33];
    int bid = blockIdx.x;
    const float* w; __nv_bfloat16 *oh, *ol;
    int N, nblk;
    if (bid < 1024)      { w = w_query; oh = wqTh; ol = wqTl; N = 1024; nblk = bid; }
    else if (bid < 2048) { w = w_to_q;  oh = wqkTh; ol = wqkTl; N = 1024; nblk = bid - 1024; }
    else if (bid < 2176) { w = w_to_k;  oh = wqkTh + (size_t)1024 * 1024;
                           ol = wqkTl + (size_t)1024 * 1024; N = 128; nblk = bid - 2048; }
    else                 { w = w_out;   oh = woTh; ol = woTl; N = 1024; nblk = bid - 2176; }

    const int nx = N / 32;
    const int n0 = (nblk % nx) * 32, k0 = (nblk / nx) * 32;
    const int tx = threadIdx.x, ty = threadIdx.y;
#pragma unroll
    for (int i = 0; i < 4; i++)
        t[ty + i * 8][tx] = w[(size_t)(k0 + ty + i * 8) * N + n0 + tx];
    __syncthreads();
#pragma unroll
    for (int i = 0; i < 4; i++) {
        const int n = n0 + ty + i * 8, k = k0 + tx;
        const float v = t[tx][ty + i * 8];
        __nv_bfloat16 h = __float2bfloat16(v);
        oh[(size_t)n * 1024 + k] = h;
        ol[(size_t)n * 1024 + k] = __float2bfloat16(v - __bfloat162float(h));
    }
}

// ---------------------------------------------------------------------------
// kproj[k,d] = sum_n proj_k[n,k] * kv[n,d]  (kv row stride kvs)
// ---------------------------------------------------------------------------
__global__ void __launch_bounds__(128) kproj_kernel(
    const float* __restrict__ kv, int kvs, const float* __restrict__ pk,
    float* __restrict__ kp)
{
    const int k = blockIdx.x;
    const int d = threadIdx.x;
    float s0 = 0.f, s1 = 0.f, s2 = 0.f, s3 = 0.f;
#pragma unroll 4
    for (int n = 0; n < N_NODES; n += 4) {
        s0 += pk[(size_t)(n + 0) * KPROJ + k] * kv[(size_t)(n + 0) * kvs + d];
        s1 += pk[(size_t)(n + 1) * KPROJ + k] * kv[(size_t)(n + 1) * kvs + d];
        s2 += pk[(size_t)(n + 2) * KPROJ + k] * kv[(size_t)(n + 2) * kvs + d];
        s3 += pk[(size_t)(n + 3) * KPROJ + k] * kv[(size_t)(n + 3) * kvs + d];
    }
    kp[(size_t)k * DH + d] = (s0 + s1) + (s2 + s3);
}

// ---------------------------------------------------------------------------
// Attention v3 (interchanged dots loop) -- unchanged from R9
// ---------------------------------------------------------------------------
#define NPB 4
#define KP_PAD 132
#define ATTN_SMEM ((KPROJ * KP_PAD + NPB * DIM + HEADS * KPROJ * NPB) * 4)

__global__ void __launch_bounds__(256) attn_v3(
    const float* __restrict__ q, int qs, const float* __restrict__ kproj,
    __nv_bfloat16* __restrict__ oh, __nv_bfloat16* __restrict__ ol)
{
    extern __shared__ float sm[];
    float* kp_s = sm;
    float* q_s  = sm + KPROJ * KP_PAD;
    float* pr_s = q_s + NPB * DIM;

    const int tid = threadIdx.x;
    const int n0 = blockIdx.x * NPB;

    for (int idx = tid; idx < KPROJ * DH; idx += 256) {
        const int r = idx >> 7, c = idx & 127;
        kp_s[r * KP_PAD + c] = kproj[idx];
    }
    for (int idx = tid; idx < NPB * DIM; idx += 256) {
        const int n = idx >> 10, hd = idx & 1023;
        q_s[hd * NPB + n] = q[(size_t)(n0 + n) * qs + hd];
    }
    __syncthreads();

    const int w = tid >> 5;
    const int l = tid & 31;
    const float scale = 0.088388347648318447f;

    float d8[NPB][8];
#pragma unroll
    for (int n = 0; n < NPB; n++)
#pragma unroll
        for (int j = 0; j < 8; j++) d8[n][j] = 0.f;

    const float* qb = q_s + w * DH * NPB;
    const float* krow = kp_s + l * KP_PAD;
    for (int d4 = 0; d4 < DH / 4; d4++) {
        const float4 q0 = *(const float4*)(qb + (d4 * 4 + 0) * NPB);
        const float4 q1 = *(const float4*)(qb + (d4 * 4 + 1) * NPB);
        const float4 q2 = *(const float4*)(qb + (d4 * 4 + 2) * NPB);
        const float4 q3 = *(const float4*)(qb + (d4 * 4 + 3) * NPB);
#pragma unroll
        for (int j = 0; j < 8; j++) {
            const float4 kk = *(const float4*)(krow + j * 32 * KP_PAD + d4 * 4);
            d8[0][j] += kk.x * q0.x + kk.y * q1.x + kk.z * q2.x + kk.w * q3.x;
            d8[1][j] += kk.x * q0.y + kk.y * q1.y + kk.z * q2.y + kk.w * q3.y;
            d8[2][j] += kk.x * q0.z + kk.y * q1.z + kk.z * q2.z + kk.w * q3.z;
            d8[3][j] += kk.x * q0.w + kk.y * q1.w + kk.z * q2.w + kk.w * q3.w;
        }
    }

#pragma unroll
    for (int n = 0; n < NPB; n++) {
        float mx = d8[n][0] * scale;
#pragma unroll
        for (int j = 0; j < 8; j++) { d8[n][j] *= scale; mx = fmaxf(mx, d8[n][j]); }
#pragma unroll
        for (int o = 16; o; o >>= 1) mx = fmaxf(mx, __shfl_xor_sync(0xFFFFFFFFu, mx, o));
        float sum = 0.f;
#pragma unroll
        for (int j = 0; j < 8; j++) { d8[n][j] = expf(d8[n][j] - mx); sum += d8[n][j]; }
#pragma unroll
        for (int o = 16; o; o >>= 1) sum += __shfl_xor_sync(0xFFFFFFFFu, sum, o);
        const float inv = 1.f / sum;
#pragma unroll
        for (int j = 0; j < 8; j++)
            pr_s[(w * KPROJ + j * 32 + l) * NPB + n] = d8[n][j] * inv;
    }
    __syncwarp();

    float4 o4[NPB];
#pragma unroll
    for (int n = 0; n < NPB; n++) o4[n] = make_float4(0.f, 0.f, 0.f, 0.f);
    const float* prb = pr_s + w * KPROJ * NPB;
#pragma unroll 4
    for (int k = 0; k < KPROJ; k++) {
        const float4 kk = *(const float4*)(kp_s + k * KP_PAD + l * 4);
        const float4 pp = *(const float4*)(prb + k * NPB);
        o4[0].x += pp.x * kk.x; o4[0].y += pp.x * kk.y;
        o4[0].z += pp.x * kk.z; o4[0].w += pp.x * kk.w;
        o4[1].x += pp.y * kk.x; o4[1].y += pp.y * kk.y;
        o4[1].z += pp.y * kk.z; o4[1].w += pp.y * kk.w;
        o4[2].x += pp.z * kk.x; o4[2].y += pp.z * kk.y;
        o4[2].z += pp.z * kk.z; o4[2].w += pp.z * kk.w;
        o4[3].x += pp.w * kk.x; o4[3].y += pp.w * kk.y;
        o4[3].z += pp.w * kk.z; o4[3].w += pp.w * kk.w;
    }

#pragma unroll
    for (int n = 0; n < NPB; n++) {
        const size_t ob = (size_t)(n0 + n) * DIM + w * DH + l * 4;
        const float v[4] = {o4[n].x, o4[n].y, o4[n].z, o4[n].w};
        __nv_bfloat16 h0 = __float2bfloat16(v[0]), h1 = __float2bfloat16(v[1]);
        __nv_bfloat16 h2 = __float2bfloat16(v[2]), h3 = __float2bfloat16(v[3]);
        *(__nv_bfloat162*)&oh[ob]     = __halves2bfloat162(h0, h1);
        *(__nv_bfloat162*)&oh[ob + 2] = __halves2bfloat162(h2, h3);
        *(__nv_bfloat162*)&ol[ob] = __halves2bfloat162(
            __float2bfloat16(v[0] - __bfloat162float(h0)),
            __float2bfloat16(v[1] - __bfloat162float(h1)));
        *(__nv_bfloat162*)&ol[ob + 2] = __halves2bfloat162(
            __float2bfloat16(v[2] - __bfloat162float(h2)),
            __float2bfloat16(v[3] - __bfloat162float(h3)));
    }
}

// ---------------------------------------------------------------------------
// LayerNorm + residual (in-place safe)
// ---------------------------------------------------------------------------
__global__ void __launch_bounds__(256) ln_res_kernel(
    const float* __restrict__ src, const float* __restrict__ resid,
    const float* __restrict__ gamma, const float* __restrict__ beta,
    float* __restrict__ dst)
{
    const int row = blockIdx.x;
    const int t = threadIdx.x;
    const float4 v = *(const float4*)&src[(size_t)row * DIM + t * 4];

    float sum = v.x + v.y + v.z + v.w;
    float sq = v.x * v.x + v.y * v.y + v.z * v.z + v.w * v.w;
#pragma unroll
    for (int o = 16; o; o >>= 1) {
        sum += __shfl_xor_sync(0xFFFFFFFFu, sum, o);
        sq  += __shfl_xor_sync(0xFFFFFFFFu, sq, o);
    }
    __shared__ float ssum[8], ssq[8];
    const int w = t >> 5, l = t & 31;
    if (l == 0) { ssum[w] = sum; ssq[w] = sq; }
    __syncthreads();
    sum = 0.f; sq = 0.f;
#pragma unroll
    for (int i = 0; i < 8; i++) { sum += ssum[i]; sq += ssq[i]; }

    const float mu = sum * (1.f / DIM);
    const float var = sq * (1.f / DIM) - mu * mu;
    const float rstd = rsqrtf(var + 1e-5f);

    const float4 g = *(const float4*)&gamma[t * 4];
    const float4 b = *(const float4*)&beta[t * 4];
    const float4 rr = *(const float4*)&resid[(size_t)row * DIM + t * 4];
    float4 o;
    o.x = (v.x - mu) * rstd * g.x + b.x + rr.x;
    o.y = (v.y - mu) * rstd * g.y + b.y + rr.y;
    o.z = (v.z - mu) * rstd * g.z + b.z + rr.z;
    o.w = (v.w - mu) * rstd * g.w + b.w + rr.w;
    *(float4*)&dst[(size_t)row * DIM + t * 4] = o;
}

// ---------------------------------------------------------------------------
// Streams/events for fork-join capture (created once at load; not device mem)
// ---------------------------------------------------------------------------
static cudaStream_t g_s2;
static cudaEvent_t g_fork, g_join;
static const bool g_init = []() {
    cudaStreamCreateWithFlags(&g_s2, cudaStreamNonBlocking);
    cudaEventCreateWithFlags(&g_fork, cudaEventDisableTiming);
    cudaEventCreateWithFlags(&g_join, cudaEventDisableTiming);
    return true;
}();

// ---------------------------------------------------------------------------
// kernel_launch
// ---------------------------------------------------------------------------
extern "C" void kernel_launch(void* const* d_in, const int* in_sizes, int n_in,
                              void* d_out, int out_size)
{
    const float* node       = (const float*)d_in[0];
    const float* edge       = (const float*)d_in[1];
    const float* w_query    = (const float*)d_in[2];
    const float* b_query    = (const float*)d_in[3];
    const float* w_edge     = (const float*)d_in[4];
    const float* b_edge     = (const float*)d_in[5];
    const float* w_to_q     = (const float*)d_in[6];
    const float* w_to_k     = (const float*)d_in[7];
    const float* proj_k     = (const float*)d_in[8];
    const float* w_out      = (const float*)d_in[9];
    const float* b_out      = (const float*)d_in[10];
    const float* gamma_node = (const float*)d_in[11];
    const float* beta_node  = (const float*)d_in[12];
    const float* gamma_edge = (const float*)d_in[13];
    const float* beta_edge  = (const float*)d_in[14];

    float* x_out = (float*)d_out;
    float* y_out = (float*)d_out + (size_t)N_NODES * DIM;

    __half *e16, *weT16;
    __nv_bfloat16 *nh, *nl, *wqTh, *wqTl;
    __nv_bfloat16 *wqkTh, *wqkTl, *woTh, *woTl, *xqh, *xql, *ah, *al;
    float *qkv, *kp, *xattn;
    cudaGetSymbolAddress((void**)&e16, g_e16);
    cudaGetSymbolAddress((void**)&weT16, g_weT16);
    cudaGetSymbolAddress((void**)&nh, g_nh);
    cudaGetSymbolAddress((void**)&nl, g_nl);
    cudaGetSymbolAddress((void**)&wqTh, g_wqT_h);
    cudaGetSymbolAddress((void**)&wqTl, g_wqT_l);
    cudaGetSymbolAddress((void**)&wqkTh, g_wqkT_h);
    cudaGetSymbolAddress((void**)&wqkTl, g_wqkT_l);
    cudaGetSymbolAddress((void**)&woTh, g_woT_h);
    cudaGetSymbolAddress((void**)&woTl, g_woT_l);
    cudaGetSymbolAddress((void**)&xqh, g_xqh);
    cudaGetSymbolAddress((void**)&xql, g_xql);
    cudaGetSymbolAddress((void**)&ah, g_ah);
    cudaGetSymbolAddress((void**)&al, g_al);
    cudaGetSymbolAddress((void**)&qkv, g_qkv);
    cudaGetSymbolAddress((void**)&kp, g_kproj);
    cudaGetSymbolAddress((void**)&xattn, g_xattn);

    static bool attr_set = false;
    if (!attr_set) {
        cudaFuncSetAttribute(gemm_bf16_sw,
                             cudaFuncAttributeMaxDynamicSharedMemorySize, N_SM);
        cudaFuncSetAttribute(gemm_f16_sw,
                             cudaFuncAttributeMaxDynamicSharedMemorySize, E_SM);
        cudaFuncSetAttribute(attn_v3,
                             cudaFuncAttributeMaxDynamicSharedMemorySize, ATTN_SMEM);
        attr_set = true;
    }

    // ---- fork: node path runs on g_s2 concurrently with edge path on default
    cudaEventRecord(g_fork, 0);
    cudaStreamWaitEvent(g_s2, g_fork, 0);

    // ---- node path (stream g_s2)
    split_node_kernel<<<NODE_F4 / 256, 256, 0, g_s2>>>(
        (const float4*)node, (__nv_bfloat162*)nh, (__nv_bfloat162*)nl);
    wprep_node_kernel<<<WPREP_NODE_BLOCKS, dim3(32, 8), 0, g_s2>>>(
        w_query, w_to_q, w_to_k, w_out,
        wqTh, wqTl, wqkTh, wqkTl, woTh, woTl);
    gemm_bf16_sw<<<dim3(8, 16), 256, N_SM, g_s2>>>(
        nh, nl, wqTh, wqTl, b_query, nullptr, xqh, xql, DIM);
    gemm_bf16_sw<<<dim3(9, 16), 256, N_SM, g_s2>>>(
        xqh, xql, wqkTh, wqkTl, nullptr, qkv, nullptr, nullptr, QKV_N);
    kproj_kernel<<<KPROJ, 128, 0, g_s2>>>(qkv + 1024, QKV_N, proj_k, kp);
    attn_v3<<<N_NODES / NPB, 256, ATTN_SMEM, g_s2>>>(qkv, QKV_N, kp, ah, al);
    gemm_bf16_sw<<<dim3(8, 16), 256, N_SM, g_s2>>>(
        ah, al, woTh, woTl, b_out, xattn, nullptr, nullptr, DIM);
    ln_res_kernel<<<N_NODES, 256, 0, g_s2>>>(
        xattn, node, gamma_node, beta_node, x_out);
    cudaEventRecord(g_join, g_s2);

    // ---- edge path (default stream)
    conv_edge_kernel<<<EDGE_F4 / 256, 256>>>((const float4*)edge, (__half2*)e16);
    wprep_edge_kernel<<<1024, dim3(32, 8)>>>(w_edge, weT16);
    gemm_f16_sw<<<dim3(8, 256), 256, E_SM>>>(e16, weT16, b_edge, y_out, DIM);
    ln_res_kernel<<<N_EDGES, 256>>>(y_out, edge, gamma_edge, beta_edge, y_out);

    // ---- join
    cudaStreamWaitEvent(0, g_join, 0);
}

// round 14
// speedup vs baseline: 1.3466x; 1.3466x over previous
#include <cuda_runtime.h>
#include <cuda_bf16.h>
#include <cuda_fp16.h>
#include <math.h>
#include <stdint.h>

#define N_NODES 1024
#define N_EDGES 32768
#define DIM     1024
#define HEADS   8
#define DH      128
#define KPROJ   256
#define QKV_N   1152   // w_to_q (1024) ++ w_to_k (128), fused GEMM

// ---------------------------------------------------------------------------
// Scratch (device globals -- no allocation allowed)
// ---------------------------------------------------------------------------
__device__ __half        g_e16[N_EDGES * DIM];                         // edge fp16
__device__ __half        g_y16[N_EDGES * DIM];                         // edge GEMM out fp16
__device__ __half        g_weT16[DIM * DIM];                           // w_edge^T fp16
__device__ __nv_bfloat16 g_nh[N_NODES * DIM],  g_nl[N_NODES * DIM];    // node hi/lo
__device__ __nv_bfloat16 g_wqT_h[DIM * DIM],   g_wqT_l[DIM * DIM];     // w_query^T
__device__ __nv_bfloat16 g_wqkT_h[QKV_N * DIM], g_wqkT_l[QKV_N * DIM]; // [w_to_q|w_to_k]^T
__device__ __nv_bfloat16 g_woT_h[DIM * DIM],   g_woT_l[DIM * DIM];     // w_out^T
__device__ __nv_bfloat16 g_xqh[N_NODES * DIM], g_xql[N_NODES * DIM];   // xq hi/lo
__device__ float         g_qkv[N_NODES * QKV_N];                       // [q | kv] fp32
__device__ float         g_kproj[KPROJ * DH];
__device__ __nv_bfloat16 g_ah[N_NODES * DIM],  g_al[N_NODES * DIM];    // attn out hi/lo
__device__ float         g_xattn[N_NODES * DIM];

// ---------------------------------------------------------------------------
// Generic-ISA PTX helpers
// ---------------------------------------------------------------------------
__device__ __forceinline__ uint32_t smem_u32(const void* p) {
    uint32_t a;
    asm("{ .reg .u64 t; cvta.to.shared.u64 t, %1; cvt.u32.u64 %0, t; }"
        : "=r"(a) : "l"(p));
    return a;
}

#define CP_ASYNC16(dst, src) \
    asm volatile("cp.async.cg.shared.global [%0], [%1], 16;" :: "r"(dst), "l"(src))
#define CP_COMMIT() asm volatile("cp.async.commit_group;" ::: "memory")
#define CP_WAIT1()  asm volatile("cp.async.wait_group 1;" ::: "memory")

#define LDSM4(r, addr) \
    asm volatile("ldmatrix.sync.aligned.m8n8.x4.shared.b16 {%0,%1,%2,%3}, [%4];" \
        : "=r"((r)[0]), "=r"((r)[1]), "=r"((r)[2]), "=r"((r)[3]) : "r"(addr))

__device__ __forceinline__ void mma16816(float* c, const uint32_t* a, const uint32_t* b) {
    asm volatile(
        "mma.sync.aligned.m16n8k16.row.col.f32.bf16.bf16.f32 "
        "{%0,%1,%2,%3}, {%4,%5,%6,%7}, {%8,%9}, {%0,%1,%2,%3};"
        : "+f"(c[0]), "+f"(c[1]), "+f"(c[2]), "+f"(c[3])
        : "r"(a[0]), "r"(a[1]), "r"(a[2]), "r"(a[3]), "r"(b[0]), "r"(b[1]));
}

__device__ __forceinline__ void mma16816h(float* c, const uint32_t* a, const uint32_t* b) {
    asm volatile(
        "mma.sync.aligned.m16n8k16.row.col.f32.f16.f16.f32 "
        "{%0,%1,%2,%3}, {%4,%5,%6,%7}, {%8,%9}, {%0,%1,%2,%3};"
        : "+f"(c[0]), "+f"(c[1]), "+f"(c[2]), "+f"(c[3])
        : "r"(a[0]), "r"(a[1]), "r"(a[2]), "r"(a[3]), "r"(b[0]), "r"(b[1]));
}

#define GK 1024

// ===========================================================================
// EDGE GEMM (fp16, 1-term, SW128 swizzle). Output: fp16 (bias added).
// ===========================================================================
#define E_NTK 16
#define E_TILE 16384
#define E_STAGE (2 * E_TILE)
#define E_SM (512 + 3 * E_STAGE)

__global__ void __launch_bounds__(256, 2) gemm_f16_sw(
    const __half* __restrict__ A16, const __half* __restrict__ BhT,
    const float* __restrict__ bias, __half* __restrict__ C16, int Nt)
{
    extern __shared__ char smem[];
    const uint32_t sb = smem_u32(smem);
    const int tid = threadIdx.x;
    const int wid = tid >> 5;
    const int lane = tid & 31;
    const int bm = blockIdx.y * 128;
    const int bn = blockIdx.x * 128;

    if (tid < 128) ((float*)smem)[tid] = bias ? bias[bn + tid] : 0.f;

    const __half* srcA = A16 + (size_t)bm * GK;
    const __half* srcB = BhT + (size_t)bn * GK;

    auto load_stage = [&](int kt, int s) {
        const uint32_t base = sb + 512 + s * E_STAGE;
#pragma unroll
        for (int i = 0; i < 4; i++) {
            const int idx = i * 256 + tid;
            const int row = idx >> 3, c = idx & 7;
            const uint32_t sw = (uint32_t)row * 128 + (uint32_t)((c ^ (row & 7)) << 4);
            CP_ASYNC16(base + sw, srcA + (size_t)row * GK + kt * 64 + c * 8);
        }
#pragma unroll
        for (int i = 0; i < 4; i++) {
            const int idx = i * 256 + tid;
            const int row = idx >> 3, c = idx & 7;
            const uint32_t sw = (uint32_t)row * 128 + (uint32_t)((c ^ (row & 7)) << 4);
            CP_ASYNC16(base + E_TILE + sw, srcB + (size_t)row * GK + kt * 64 + c * 8);
        }
    };

    load_stage(0, 0); CP_COMMIT();
    load_stage(1, 1); CP_COMMIT();

    const int wm = (wid >> 2) * 64;
    const int wn = (wid & 3) * 32;
    const int l7 = lane & 7;
    const int brow_off = l7 + ((lane >> 4) << 3);

    float acc[4][4][4];
#pragma unroll
    for (int mt = 0; mt < 4; mt++)
#pragma unroll
        for (int nt = 0; nt < 4; nt++)
#pragma unroll
            for (int j = 0; j < 4; j++) acc[mt][nt][j] = 0.f;

    for (int kt = 0; kt < E_NTK; kt++) {
        CP_WAIT1();
        __syncthreads();

        if (kt + 2 < E_NTK) { load_stage(kt + 2, (kt + 2) % 3); CP_COMMIT(); }

        const uint32_t st = sb + 512 + (kt % 3) * E_STAGE;
        const uint32_t aRow = st + (uint32_t)(wm + (lane & 15)) * 128;
        const uint32_t bRowBase = st + E_TILE + (uint32_t)(wn + brow_off) * 128;

#pragma unroll
        for (int kh = 0; kh < 4; kh++) {
            const uint32_t aChunk = (uint32_t)(((kh << 1) | (lane >> 4)) ^ l7) << 4;
            const uint32_t bChunk = (uint32_t)(((kh << 1) | ((lane >> 3) & 1)) ^ l7) << 4;
            uint32_t aF[4][4], bF[2][4];
#pragma unroll
            for (int p = 0; p < 2; p++)
                LDSM4(bF[p], bRowBase + (uint32_t)(p * 16) * 128 + bChunk);
#pragma unroll
            for (int mt = 0; mt < 4; mt++)
                LDSM4(aF[mt], aRow + (uint32_t)(mt * 16) * 128 + aChunk);
#pragma unroll
            for (int mt = 0; mt < 4; mt++)
#pragma unroll
                for (int nt = 0; nt < 4; nt++)
                    mma16816h(acc[mt][nt], aF[mt], &bF[nt >> 1][(nt & 1) * 2]);
        }
    }

    const float* bs = (const float*)smem;
#pragma unroll
    for (int mt = 0; mt < 4; mt++) {
#pragma unroll
        for (int nt = 0; nt < 4; nt++) {
            const int c = wn + nt * 8 + (lane & 3) * 2;
            const size_t r0 = (size_t)bm + wm + mt * 16 + (lane >> 2);
            *(__half2*)&C16[r0 * Nt + bn + c] = __floats2half2_rn(
                acc[mt][nt][0] + bs[c], acc[mt][nt][1] + bs[c + 1]);
            *(__half2*)&C16[(r0 + 8) * Nt + bn + c] = __floats2half2_rn(
                acc[mt][nt][2] + bs[c], acc[mt][nt][3] + bs[c + 1]);
        }
    }
}

// ===========================================================================
// NODE GEMM (bf16 3-term, SW128 swizzle) -- unchanged (proven)
// ===========================================================================
#define N_NTK 16
#define N_ATILE 8192
#define N_BTILE 16384
#define N_STAGE (2 * N_ATILE + 2 * N_BTILE)
#define N_SM (512 + 3 * N_STAGE)

__global__ void __launch_bounds__(256, 1) gemm_bf16_sw(
    const __nv_bfloat16* __restrict__ Ah, const __nv_bfloat16* __restrict__ Al,
    const __nv_bfloat16* __restrict__ BhT, const __nv_bfloat16* __restrict__ BlT,
    const float* __restrict__ bias,
    float* __restrict__ Cf, __nv_bfloat16* __restrict__ Ch, __nv_bfloat16* __restrict__ Cl,
    int Nt)
{
    extern __shared__ char smem[];
    const uint32_t sb = smem_u32(smem);
    const int tid = threadIdx.x;
    const int wid = tid >> 5;
    const int lane = tid & 31;
    const int bm = blockIdx.y * 64;
    const int bn = blockIdx.x * 128;

    if (tid < 128) ((float*)smem)[tid] = bias ? bias[bn + tid] : 0.f;

    const __nv_bfloat16* sAh = Ah + (size_t)bm * GK;
    const __nv_bfloat16* sAl = Al + (size_t)bm * GK;
    const __nv_bfloat16* sBh = BhT + (size_t)bn * GK;
    const __nv_bfloat16* sBl = BlT + (size_t)bn * GK;

    auto load_stage = [&](int kt, int s) {
        const uint32_t base = sb + 512 + s * N_STAGE;
#pragma unroll
        for (int i = 0; i < 2; i++) {
            const int idx = i * 256 + tid;
            const int row = idx >> 3, c = idx & 7;
            const uint32_t sw = (uint32_t)row * 128 + (uint32_t)((c ^ (row & 7)) << 4);
            CP_ASYNC16(base + sw, sAh + (size_t)row * GK + kt * 64 + c * 8);
            CP_ASYNC16(base + N_ATILE + sw, sAl + (size_t)row * GK + kt * 64 + c * 8);
        }
#pragma unroll
        for (int i = 0; i < 4; i++) {
            const int idx = i * 256 + tid;
            const int row = idx >> 3, c = idx & 7;
            const uint32_t sw = (uint32_t)row * 128 + (uint32_t)((c ^ (row & 7)) << 4);
            CP_ASYNC16(base + 2 * N_ATILE + sw, sBh + (size_t)row * GK + kt * 64 + c * 8);
            CP_ASYNC16(base + 2 * N_ATILE + N_BTILE + sw,
                       sBl + (size_t)row * GK + kt * 64 + c * 8);
        }
    };

    load_stage(0, 0); CP_COMMIT();
    load_stage(1, 1); CP_COMMIT();

    const int wm = (wid >> 2) * 32;
    const int wn = (wid & 3) * 32;
    const int l7 = lane & 7;
    const int brow_off = l7 + ((lane >> 4) << 3);

    float acc[2][4][4];
#pragma unroll
    for (int mt = 0; mt < 2; mt++)
#pragma unroll
        for (int nt = 0; nt < 4; nt++)
#pragma unroll
            for (int j = 0; j < 4; j++) acc[mt][nt][j] = 0.f;

    for (int kt = 0; kt < N_NTK; kt++) {
        CP_WAIT1();
        __syncthreads();

        if (kt + 2 < N_NTK) { load_stage(kt + 2, (kt + 2) % 3); CP_COMMIT(); }

        const uint32_t st = sb + 512 + (kt % 3) * N_STAGE;
        const uint32_t ahRow = st + (uint32_t)(wm + (lane & 15)) * 128;
        const uint32_t alRow = ahRow + N_ATILE;
        const uint32_t bhRowBase = st + 2 * N_ATILE + (uint32_t)(wn + brow_off) * 128;
        const uint32_t blRowBase = bhRowBase + N_BTILE;

#pragma unroll
        for (int kh = 0; kh < 4; kh++) {
            const uint32_t aChunk = (uint32_t)(((kh << 1) | (lane >> 4)) ^ l7) << 4;
            const uint32_t bChunk = (uint32_t)(((kh << 1) | ((lane >> 3) & 1)) ^ l7) << 4;
            uint32_t aH[2][4], aL[2][4], bHF[2][4], bLF[2][4];
#pragma unroll
            for (int p = 0; p < 2; p++) {
                LDSM4(bHF[p], bhRowBase + (uint32_t)(p * 16) * 128 + bChunk);
                LDSM4(bLF[p], blRowBase + (uint32_t)(p * 16) * 128 + bChunk);
            }
#pragma unroll
            for (int mt = 0; mt < 2; mt++) {
                LDSM4(aH[mt], ahRow + (uint32_t)(mt * 16) * 128 + aChunk);
                LDSM4(aL[mt], alRow + (uint32_t)(mt * 16) * 128 + aChunk);
            }
#pragma unroll
            for (int mt = 0; mt < 2; mt++)
#pragma unroll
                for (int nt = 0; nt < 4; nt++) {
                    const uint32_t* bh = &bHF[nt >> 1][(nt & 1) * 2];
                    const uint32_t* bl = &bLF[nt >> 1][(nt & 1) * 2];
                    mma16816(acc[mt][nt], aH[mt], bh);
                    mma16816(acc[mt][nt], aH[mt], bl);
                    mma16816(acc[mt][nt], aL[mt], bh);
                }
        }
    }

    const float* bs = (const float*)smem;
#pragma unroll
    for (int mt = 0; mt < 2; mt++) {
#pragma unroll
        for (int nt = 0; nt < 4; nt++) {
            const int c = wn + nt * 8 + (lane & 3) * 2;
            const size_t r0 = (size_t)bm + wm + mt * 16 + (lane >> 2);
            const float v0 = acc[mt][nt][0] + bs[c];
            const float v1 = acc[mt][nt][1] + bs[c + 1];
            const float v2 = acc[mt][nt][2] + bs[c];
            const float v3 = acc[mt][nt][3] + bs[c + 1];
            if (Cf) {
                *(float2*)&Cf[r0 * Nt + bn + c]       = make_float2(v0, v1);
                *(float2*)&Cf[(r0 + 8) * Nt + bn + c] = make_float2(v2, v3);
            }
            if (Ch) {
                __nv_bfloat16 h0 = __float2bfloat16(v0), h1 = __float2bfloat16(v1);
                __nv_bfloat16 h2 = __float2bfloat16(v2), h3 = __float2bfloat16(v3);
                *(__nv_bfloat162*)&Ch[r0 * Nt + bn + c] = __halves2bfloat162(h0, h1);
                *(__nv_bfloat162*)&Ch[(r0 + 8) * Nt + bn + c] = __halves2bfloat162(h2, h3);
                *(__nv_bfloat162*)&Cl[r0 * Nt + bn + c] = __halves2bfloat162(
                    __float2bfloat16(v0 - __bfloat162float(h0)),
                    __float2bfloat16(v1 - __bfloat162float(h1)));
                *(__nv_bfloat162*)&Cl[(r0 + 8) * Nt + bn + c] = __halves2bfloat162(
                    __float2bfloat16(v2 - __bfloat162float(h2)),
                    __float2bfloat16(v3 - __bfloat162float(h3)));
            }
        }
    }
}

// ---------------------------------------------------------------------------
// Fused elementwise: edge fp32 -> fp16; node fp32 -> bf16 hi/lo.
// ---------------------------------------------------------------------------
#define EDGE_F4 (N_EDGES * DIM / 4)
#define NODE_F4 (N_NODES * DIM / 4)
#define CONV_BLOCKS (EDGE_F4 / 256 + NODE_F4 / 256)

__global__ void __launch_bounds__(256) fused_conv_kernel(
    const float4* __restrict__ edge, __half2* __restrict__ e16,
    const float4* __restrict__ node, __nv_bfloat162* __restrict__ nh,
    __nv_bfloat162* __restrict__ nl)
{
    const int bid = blockIdx.x;
    if (bid < EDGE_F4 / 256) {
        const int i = bid * 256 + threadIdx.x;
        float4 v = edge[i];
        e16[2 * i + 0] = __halves2half2(__float2half(v.x), __float2half(v.y));
        e16[2 * i + 1] = __halves2half2(__float2half(v.z), __float2half(v.w));
    } else {
        const int i = (bid - EDGE_F4 / 256) * 256 + threadIdx.x;
        float4 v = node[i];
        __nv_bfloat16 h0 = __float2bfloat16(v.x), h1 = __float2bfloat16(v.y);
        __nv_bfloat16 h2 = __float2bfloat16(v.z), h3 = __float2bfloat16(v.w);
        nh[2 * i + 0] = __halves2bfloat162(h0, h1);
        nh[2 * i + 1] = __halves2bfloat162(h2, h3);
        nl[2 * i + 0] = __halves2bfloat162(
            __float2bfloat16(v.x - __bfloat162float(h0)),
            __float2bfloat16(v.y - __bfloat162float(h1)));
        nl[2 * i + 1] = __halves2bfloat162(
            __float2bfloat16(v.z - __bfloat162float(h2)),
            __float2bfloat16(v.w - __bfloat162float(h3)));
    }
}

// ---------------------------------------------------------------------------
// Fused weight prep: 5 transpose jobs in one kernel. Block (32,8).
// ---------------------------------------------------------------------------
#define WPREP_BLOCKS (1024 * 4 + 128)

__global__ void __launch_bounds__(256) fused_wprep_kernel(
    const float* __restrict__ w_query, const float* __restrict__ w_to_q,
    const float* __restrict__ w_to_k, const float* __restrict__ w_out,
    const float* __restrict__ w_edge,
    __nv_bfloat16* __restrict__ wqTh, __nv_bfloat16* __restrict__ wqTl,
    __nv_bfloat16* __restrict__ wqkTh, __nv_bfloat16* __restrict__ wqkTl,
    __nv_bfloat16* __restrict__ woTh, __nv_bfloat16* __restrict__ woTl,
    __half* __restrict__ weT16)
{
    __shared__ float t[32][33];
    int bid = blockIdx.x;
    const float* w; __nv_bfloat16 *oh = nullptr, *ol = nullptr; __half* of16 = nullptr;
    int N, nblk;
    if (bid < 1024)      { w = w_query; oh = wqTh; ol = wqTl; N = 1024; nblk = bid; }
    else if (bid < 2048) { w = w_to_q;  oh = wqkTh; ol = wqkTl; N = 1024; nblk = bid - 1024; }
    else if (bid < 2176) { w = w_to_k;  oh = wqkTh + (size_t)1024 * 1024;
                           ol = wqkTl + (size_t)1024 * 1024; N = 128; nblk = bid - 2048; }
    else if (bid < 3200) { w = w_out;   oh = woTh; ol = woTl; N = 1024; nblk = bid - 2176; }
    else                 { w = w_edge;  of16 = weT16; N = 1024; nblk = bid - 3200; }

    const int nx = N / 32;
    const int n0 = (nblk % nx) * 32, k0 = (nblk / nx) * 32;
    const int tx = threadIdx.x, ty = threadIdx.y;
#pragma unroll
    for (int i = 0; i < 4; i++)
        t[ty + i * 8][tx] = w[(size_t)(k0 + ty + i * 8) * N + n0 + tx];
    __syncthreads();
#pragma unroll
    for (int i = 0; i < 4; i++) {
        const int n = n0 + ty + i * 8, k = k0 + tx;
        const float v = t[tx][ty + i * 8];
        if (of16) {
            of16[(size_t)n * 1024 + k] = __float2half(v);
        } else {
            __nv_bfloat16 h = __float2bfloat16(v);
            oh[(size_t)n * 1024 + k] = h;
            ol[(size_t)n * 1024 + k] = __float2bfloat16(v - __bfloat162float(h));
        }
    }
}

// ---------------------------------------------------------------------------
// kproj[k,d] = sum_n proj_k[n,k] * kv[n,d]  (kv row stride kvs)
// ---------------------------------------------------------------------------
__global__ void __launch_bounds__(128) kproj_kernel(
    const float* __restrict__ kv, int kvs, const float* __restrict__ pk,
    float* __restrict__ kp)
{
    const int k = blockIdx.x;
    const int d = threadIdx.x;
    float s0 = 0.f, s1 = 0.f, s2 = 0.f, s3 = 0.f;
#pragma unroll 4
    for (int n = 0; n < N_NODES; n += 4) {
        s0 += pk[(size_t)(n + 0) * KPROJ + k] * kv[(size_t)(n + 0) * kvs + d];
        s1 += pk[(size_t)(n + 1) * KPROJ + k] * kv[(size_t)(n + 1) * kvs + d];
        s2 += pk[(size_t)(n + 2) * KPROJ + k] * kv[(size_t)(n + 2) * kvs + d];
        s3 += pk[(size_t)(n + 3) * KPROJ + k] * kv[(size_t)(n + 3) * kvs + d];
    }
    kp[(size_t)k * DH + d] = (s0 + s1) + (s2 + s3);
}

// ---------------------------------------------------------------------------
// Attention v3 (interchanged dots loop) -- unchanged from R9
// ---------------------------------------------------------------------------
#define NPB 4
#define KP_PAD 132
#define ATTN_SMEM ((KPROJ * KP_PAD + NPB * DIM + HEADS * KPROJ * NPB) * 4)

__global__ void __launch_bounds__(256) attn_v3(
    const float* __restrict__ q, int qs, const float* __restrict__ kproj,
    __nv_bfloat16* __restrict__ oh, __nv_bfloat16* __restrict__ ol)
{
    extern __shared__ float sm[];
    float* kp_s = sm;
    float* q_s  = sm + KPROJ * KP_PAD;
    float* pr_s = q_s + NPB * DIM;

    const int tid = threadIdx.x;
    const int n0 = blockIdx.x * NPB;

    for (int idx = tid; idx < KPROJ * DH; idx += 256) {
        const int r = idx >> 7, c = idx & 127;
        kp_s[r * KP_PAD + c] = kproj[idx];
    }
    for (int idx = tid; idx < NPB * DIM; idx += 256) {
        const int n = idx >> 10, hd = idx & 1023;
        q_s[hd * NPB + n] = q[(size_t)(n0 + n) * qs + hd];
    }
    __syncthreads();

    const int w = tid >> 5;
    const int l = tid & 31;
    const float scale = 0.088388347648318447f;

    float d8[NPB][8];
#pragma unroll
    for (int n = 0; n < NPB; n++)
#pragma unroll
        for (int j = 0; j < 8; j++) d8[n][j] = 0.f;

    const float* qb = q_s + w * DH * NPB;
    const float* krow = kp_s + l * KP_PAD;
    for (int d4 = 0; d4 < DH / 4; d4++) {
        const float4 q0 = *(const float4*)(qb + (d4 * 4 + 0) * NPB);
        const float4 q1 = *(const float4*)(qb + (d4 * 4 + 1) * NPB);
        const float4 q2 = *(const float4*)(qb + (d4 * 4 + 2) * NPB);
        const float4 q3 = *(const float4*)(qb + (d4 * 4 + 3) * NPB);
#pragma unroll
        for (int j = 0; j < 8; j++) {
            const float4 kk = *(const float4*)(krow + j * 32 * KP_PAD + d4 * 4);
            d8[0][j] += kk.x * q0.x + kk.y * q1.x + kk.z * q2.x + kk.w * q3.x;
            d8[1][j] += kk.x * q0.y + kk.y * q1.y + kk.z * q2.y + kk.w * q3.y;
            d8[2][j] += kk.x * q0.z + kk.y * q1.z + kk.z * q2.z + kk.w * q3.z;
            d8[3][j] += kk.x * q0.w + kk.y * q1.w + kk.z * q2.w + kk.w * q3.w;
        }
    }

#pragma unroll
    for (int n = 0; n < NPB; n++) {
        float mx = d8[n][0] * scale;
#pragma unroll
        for (int j = 0; j < 8; j++) { d8[n][j] *= scale; mx = fmaxf(mx, d8[n][j]); }
#pragma unroll
        for (int o = 16; o; o >>= 1) mx = fmaxf(mx, __shfl_xor_sync(0xFFFFFFFFu, mx, o));
        float sum = 0.f;
#pragma unroll
        for (int j = 0; j < 8; j++) { d8[n][j] = expf(d8[n][j] - mx); sum += d8[n][j]; }
#pragma unroll
        for (int o = 16; o; o >>= 1) sum += __shfl_xor_sync(0xFFFFFFFFu, sum, o);
        const float inv = 1.f / sum;
#pragma unroll
        for (int j = 0; j < 8; j++)
            pr_s[(w * KPROJ + j * 32 + l) * NPB + n] = d8[n][j] * inv;
    }
    __syncwarp();

    float4 o4[NPB];
#pragma unroll
    for (int n = 0; n < NPB; n++) o4[n] = make_float4(0.f, 0.f, 0.f, 0.f);
    const float* prb = pr_s + w * KPROJ * NPB;
#pragma unroll 4
    for (int k = 0; k < KPROJ; k++) {
        const float4 kk = *(const float4*)(kp_s + k * KP_PAD + l * 4);
        const float4 pp = *(const float4*)(prb + k * NPB);
        o4[0].x += pp.x * kk.x; o4[0].y += pp.x * kk.y;
        o4[0].z += pp.x * kk.z; o4[0].w += pp.x * kk.w;
        o4[1].x += pp.y * kk.x; o4[1].y += pp.y * kk.y;
        o4[1].z += pp.y * kk.z; o4[1].w += pp.y * kk.w;
        o4[2].x += pp.z * kk.x; o4[2].y += pp.z * kk.y;
        o4[2].z += pp.z * kk.z; o4[2].w += pp.z * kk.w;
        o4[3].x += pp.w * kk.x; o4[3].y += pp.w * kk.y;
        o4[3].z += pp.w * kk.z; o4[3].w += pp.w * kk.w;
    }

#pragma unroll
    for (int n = 0; n < NPB; n++) {
        const size_t ob = (size_t)(n0 + n) * DIM + w * DH + l * 4;
        const float v[4] = {o4[n].x, o4[n].y, o4[n].z, o4[n].w};
        __nv_bfloat16 h0 = __float2bfloat16(v[0]), h1 = __float2bfloat16(v[1]);
        __nv_bfloat16 h2 = __float2bfloat16(v[2]), h3 = __float2bfloat16(v[3]);
        *(__nv_bfloat162*)&oh[ob]     = __halves2bfloat162(h0, h1);
        *(__nv_bfloat162*)&oh[ob + 2] = __halves2bfloat162(h2, h3);
        *(__nv_bfloat162*)&ol[ob] = __halves2bfloat162(
            __float2bfloat16(v[0] - __bfloat162float(h0)),
            __float2bfloat16(v[1] - __bfloat162float(h1)));
        *(__nv_bfloat162*)&ol[ob + 2] = __halves2bfloat162(
            __float2bfloat16(v[2] - __bfloat162float(h2)),
            __float2bfloat16(v[3] - __bfloat162float(h3)));
    }
}

// ---------------------------------------------------------------------------
// LayerNorm + residual, fp32 src (node path)
// ---------------------------------------------------------------------------
__global__ void __launch_bounds__(256) ln_res_kernel(
    const float* __restrict__ src, const float* __restrict__ resid,
    const float* __restrict__ gamma, const float* __restrict__ beta,
    float* __restrict__ dst)
{
    const int row = blockIdx.x;
    const int t = threadIdx.x;
    const float4 v = *(const float4*)&src[(size_t)row * DIM + t * 4];

    float sum = v.x + v.y + v.z + v.w;
    float sq = v.x * v.x + v.y * v.y + v.z * v.z + v.w * v.w;
#pragma unroll
    for (int o = 16; o; o >>= 1) {
        sum += __shfl_xor_sync(0xFFFFFFFFu, sum, o);
        sq  += __shfl_xor_sync(0xFFFFFFFFu, sq, o);
    }
    __shared__ float ssum[8], ssq[8];
    const int w = t >> 5, l = t & 31;
    if (l == 0) { ssum[w] = sum; ssq[w] = sq; }
    __syncthreads();
    sum = 0.f; sq = 0.f;
#pragma unroll
    for (int i = 0; i < 8; i++) { sum += ssum[i]; sq += ssq[i]; }

    const float mu = sum * (1.f / DIM);
    const float var = sq * (1.f / DIM) - mu * mu;
    const float rstd = rsqrtf(var + 1e-5f);

    const float4 g = *(const float4*)&gamma[t * 4];
    const float4 b = *(const float4*)&beta[t * 4];
    const float4 rr = *(const float4*)&resid[(size_t)row * DIM + t * 4];
    float4 o;
    o.x = (v.x - mu) * rstd * g.x + b.x + rr.x;
    o.y = (v.y - mu) * rstd * g.y + b.y + rr.y;
    o.z = (v.z - mu) * rstd * g.z + b.z + rr.z;
    o.w = (v.w - mu) * rstd * g.w + b.w + rr.w;
    *(float4*)&dst[(size_t)row * DIM + t * 4] = o;
}

// ---------------------------------------------------------------------------
// LayerNorm + residual, fp16 src (edge path) -> fp32 out
// ---------------------------------------------------------------------------
__global__ void __launch_bounds__(256) ln_res_h_kernel(
    const __half* __restrict__ src, const float* __restrict__ resid,
    const float* __restrict__ gamma, const float* __restrict__ beta,
    float* __restrict__ dst)
{
    const int row = blockIdx.x;
    const int t = threadIdx.x;
    const __half2 h01 = *(const __half2*)&src[(size_t)row * DIM + t * 4];
    const __half2 h23 = *(const __half2*)&src[(size_t)row * DIM + t * 4 + 2];
    const float2 f01 = __half22float2(h01);
    const float2 f23 = __half22float2(h23);
    float4 v = make_float4(f01.x, f01.y, f23.x, f23.y);

    float sum = v.x + v.y + v.z + v.w;
    float sq = v.x * v.x + v.y * v.y + v.z * v.z + v.w * v.w;
#pragma unroll
    for (int o = 16; o; o >>= 1) {
        sum += __shfl_xor_sync(0xFFFFFFFFu, sum, o);
        sq  += __shfl_xor_sync(0xFFFFFFFFu, sq, o);
    }
    __shared__ float ssum[8], ssq[8];
    const int w = t >> 5, l = t & 31;
    if (l == 0) { ssum[w] = sum; ssq[w] = sq; }
    __syncthreads();
    sum = 0.f; sq = 0.f;
#pragma unroll
    for (int i = 0; i < 8; i++) { sum += ssum[i]; sq += ssq[i]; }

    const float mu = sum * (1.f / DIM);
    const float var = sq * (1.f / DIM) - mu * mu;
    const float rstd = rsqrtf(var + 1e-5f);

    const float4 g = *(const float4*)&gamma[t * 4];
    const float4 b = *(const float4*)&beta[t * 4];
    const float4 rr = *(const float4*)&resid[(size_t)row * DIM + t * 4];
    float4 o;
    o.x = (v.x - mu) * rstd * g.x + b.x + rr.x;
    o.y = (v.y - mu) * rstd * g.y + b.y + rr.y;
    o.z = (v.z - mu) * rstd * g.z + b.z + rr.z;
    o.w = (v.w - mu) * rstd * g.w + b.w + rr.w;
    *(float4*)&dst[(size_t)row * DIM + t * 4] = o;
}

// ---------------------------------------------------------------------------
// kernel_launch (single stream, R9 structure)
// ---------------------------------------------------------------------------
extern "C" void kernel_launch(void* const* d_in, const int* in_sizes, int n_in,
                              void* d_out, int out_size)
{
    const float* node       = (const float*)d_in[0];
    const float* edge       = (const float*)d_in[1];
    const float* w_query    = (const float*)d_in[2];
    const float* b_query    = (const float*)d_in[3];
    const float* w_edge     = (const float*)d_in[4];
    const float* b_edge     = (const float*)d_in[5];
    const float* w_to_q     = (const float*)d_in[6];
    const float* w_to_k     = (const float*)d_in[7];
    const float* proj_k     = (const float*)d_in[8];
    const float* w_out      = (const float*)d_in[9];
    const float* b_out      = (const float*)d_in[10];
    const float* gamma_node = (const float*)d_in[11];
    const float* beta_node  = (const float*)d_in[12];
    const float* gamma_edge = (const float*)d_in[13];
    const float* beta_edge  = (const float*)d_in[14];

    float* x_out = (float*)d_out;
    float* y_out = (float*)d_out + (size_t)N_NODES * DIM;

    __half *e16, *y16, *weT16;
    __nv_bfloat16 *nh, *nl, *wqTh, *wqTl;
    __nv_bfloat16 *wqkTh, *wqkTl, *woTh, *woTl, *xqh, *xql, *ah, *al;
    float *qkv, *kp, *xattn;
    cudaGetSymbolAddress((void**)&e16, g_e16);
    cudaGetSymbolAddress((void**)&y16, g_y16);
    cudaGetSymbolAddress((void**)&weT16, g_weT16);
    cudaGetSymbolAddress((void**)&nh, g_nh);
    cudaGetSymbolAddress((void**)&nl, g_nl);
    cudaGetSymbolAddress((void**)&wqTh, g_wqT_h);
    cudaGetSymbolAddress((void**)&wqTl, g_wqT_l);
    cudaGetSymbolAddress((void**)&wqkTh, g_wqkT_h);
    cudaGetSymbolAddress((void**)&wqkTl, g_wqkT_l);
    cudaGetSymbolAddress((void**)&woTh, g_woT_h);
    cudaGetSymbolAddress((void**)&woTl, g_woT_l);
    cudaGetSymbolAddress((void**)&xqh, g_xqh);
    cudaGetSymbolAddress((void**)&xql, g_xql);
    cudaGetSymbolAddress((void**)&ah, g_ah);
    cudaGetSymbolAddress((void**)&al, g_al);
    cudaGetSymbolAddress((void**)&qkv, g_qkv);
    cudaGetSymbolAddress((void**)&kp, g_kproj);
    cudaGetSymbolAddress((void**)&xattn, g_xattn);

    static bool attr_set = false;
    if (!attr_set) {
        cudaFuncSetAttribute(gemm_bf16_sw,
                             cudaFuncAttributeMaxDynamicSharedMemorySize, N_SM);
        cudaFuncSetAttribute(gemm_f16_sw,
                             cudaFuncAttributeMaxDynamicSharedMemorySize, E_SM);
        cudaFuncSetAttribute(attn_v3,
                             cudaFuncAttributeMaxDynamicSharedMemorySize, ATTN_SMEM);
        attr_set = true;
    }

    // 1. fused elementwise converts
    fused_conv_kernel<<<CONV_BLOCKS, 256>>>(
        (const float4*)edge, (__half2*)e16,
        (const float4*)node, (__nv_bfloat162*)nh, (__nv_bfloat162*)nl);
    // 2. fused weight prep
    fused_wprep_kernel<<<WPREP_BLOCKS, dim3(32, 8)>>>(
        w_query, w_to_q, w_to_k, w_out, w_edge,
        wqTh, wqTl, wqkTh, wqkTl, woTh, woTl, weT16);
    // 3. node GEMM #1 (xq)
    gemm_bf16_sw<<<dim3(8, 16), 256, N_SM>>>(
        nh, nl, wqTh, wqTl, b_query, nullptr, xqh, xql, DIM);
    // 4. edge GEMM -> fp16 intermediate (profiled slot)
    gemm_f16_sw<<<dim3(8, 256), 256, E_SM>>>(e16, weT16, b_edge, y16, DIM);
    // 5. edge LN (fp16 src -> fp32 out)
    ln_res_h_kernel<<<N_EDGES, 256>>>(y16, edge, gamma_edge, beta_edge, y_out);
    // 6. node GEMM #2 (qkv)
    gemm_bf16_sw<<<dim3(9, 16), 256, N_SM>>>(
        xqh, xql, wqkTh, wqkTl, nullptr, qkv, nullptr, nullptr, QKV_N);
    // 7-8. kproj + attention
    kproj_kernel<<<KPROJ, 128>>>(qkv + 1024, QKV_N, proj_k, kp);
    attn_v3<<<N_NODES / NPB, 256, ATTN_SMEM>>>(qkv, QKV_N, kp, ah, al);
    // 9. node GEMM #3 (x_attn)
    gemm_bf16_sw<<<dim3(8, 16), 256, N_SM>>>(
        ah, al, woTh, woTl, b_out, xattn, nullptr, nullptr, DIM);
    // 10. node LN
    ln_res_kernel<<<N_NODES, 256>>>(xattn, node, gamma_node, beta_node, x_out);
}

// round 15
// speedup vs baseline: 1.4080x; 1.0456x over previous
#include <cuda_runtime.h>
#include <cuda_bf16.h>
#include <cuda_fp16.h>
#include <math.h>
#include <stdint.h>

#define N_NODES 1024
#define N_EDGES 32768
#define DIM     1024
#define HEADS   8
#define DH      128
#define KPROJ   256
#define QKV_N   1152   // w_to_q (1024) ++ w_to_k (128), fused GEMM

// ---------------------------------------------------------------------------
// Scratch (device globals -- no allocation allowed)
// ---------------------------------------------------------------------------
__device__ __half g_e16[N_EDGES * DIM];                      // edge fp16
__device__ __half g_y16[N_EDGES * DIM];                      // edge GEMM out fp16
__device__ __half g_weT16[DIM * DIM];                        // w_edge^T fp16
__device__ __half g_nh16[N_NODES * DIM], g_nl16[N_NODES * DIM]; // node fp16 hi/lo
__device__ __half g_wqT16[DIM * DIM];                        // w_query^T fp16
__device__ __half g_wqkT16[QKV_N * DIM];                     // [w_to_q|w_to_k]^T fp16
__device__ __half g_woT16[DIM * DIM];                        // w_out^T fp16
__device__ __half g_xqh16[N_NODES * DIM], g_xql16[N_NODES * DIM]; // xq fp16 hi/lo
__device__ float  g_qkv[N_NODES * QKV_N];                    // [q | kv] fp32
__device__ float  g_kproj[KPROJ * DH];
__device__ __half g_ah16[N_NODES * DIM], g_al16[N_NODES * DIM];  // attn out fp16 hi/lo
__device__ float  g_xattn[N_NODES * DIM];

// ---------------------------------------------------------------------------
// Generic-ISA PTX helpers
// ---------------------------------------------------------------------------
__device__ __forceinline__ uint32_t smem_u32(const void* p) {
    uint32_t a;
    asm("{ .reg .u64 t; cvta.to.shared.u64 t, %1; cvt.u32.u64 %0, t; }"
        : "=r"(a) : "l"(p));
    return a;
}

#define CP_ASYNC16(dst, src) \
    asm volatile("cp.async.cg.shared.global [%0], [%1], 16;" :: "r"(dst), "l"(src))
#define CP_COMMIT() asm volatile("cp.async.commit_group;" ::: "memory")
#define CP_WAIT1()  asm volatile("cp.async.wait_group 1;" ::: "memory")

#define LDSM4(r, addr) \
    asm volatile("ldmatrix.sync.aligned.m8n8.x4.shared.b16 {%0,%1,%2,%3}, [%4];" \
        : "=r"((r)[0]), "=r"((r)[1]), "=r"((r)[2]), "=r"((r)[3]) : "r"(addr))

__device__ __forceinline__ void mma16816h(float* c, const uint32_t* a, const uint32_t* b) {
    asm volatile(
        "mma.sync.aligned.m16n8k16.row.col.f32.f16.f16.f32 "
        "{%0,%1,%2,%3}, {%4,%5,%6,%7}, {%8,%9}, {%0,%1,%2,%3};"
        : "+f"(c[0]), "+f"(c[1]), "+f"(c[2]), "+f"(c[3])
        : "r"(a[0]), "r"(a[1]), "r"(a[2]), "r"(a[3]), "r"(b[0]), "r"(b[1]));
}

#define GK 1024

// ===========================================================================
// EDGE GEMM (fp16, 1-term, SW128 swizzle). Output fp16. Unchanged (proven).
// ===========================================================================
#define E_NTK 16
#define E_TILE 16384
#define E_STAGE (2 * E_TILE)
#define E_SM (512 + 3 * E_STAGE)

__global__ void __launch_bounds__(256, 2) gemm_f16_sw(
    const __half* __restrict__ A16, const __half* __restrict__ BhT,
    const float* __restrict__ bias, __half* __restrict__ C16, int Nt)
{
    extern __shared__ char smem[];
    const uint32_t sb = smem_u32(smem);
    const int tid = threadIdx.x;
    const int wid = tid >> 5;
    const int lane = tid & 31;
    const int bm = blockIdx.y * 128;
    const int bn = blockIdx.x * 128;

    if (tid < 128) ((float*)smem)[tid] = bias ? bias[bn + tid] : 0.f;

    const __half* srcA = A16 + (size_t)bm * GK;
    const __half* srcB = BhT + (size_t)bn * GK;

    auto load_stage = [&](int kt, int s) {
        const uint32_t base = sb + 512 + s * E_STAGE;
#pragma unroll
        for (int i = 0; i < 4; i++) {
            const int idx = i * 256 + tid;
            const int row = idx >> 3, c = idx & 7;
            const uint32_t sw = (uint32_t)row * 128 + (uint32_t)((c ^ (row & 7)) << 4);
            CP_ASYNC16(base + sw, srcA + (size_t)row * GK + kt * 64 + c * 8);
        }
#pragma unroll
        for (int i = 0; i < 4; i++) {
            const int idx = i * 256 + tid;
            const int row = idx >> 3, c = idx & 7;
            const uint32_t sw = (uint32_t)row * 128 + (uint32_t)((c ^ (row & 7)) << 4);
            CP_ASYNC16(base + E_TILE + sw, srcB + (size_t)row * GK + kt * 64 + c * 8);
        }
    };

    load_stage(0, 0); CP_COMMIT();
    load_stage(1, 1); CP_COMMIT();

    const int wm = (wid >> 2) * 64;
    const int wn = (wid & 3) * 32;
    const int l7 = lane & 7;
    const int brow_off = l7 + ((lane >> 4) << 3);

    float acc[4][4][4];
#pragma unroll
    for (int mt = 0; mt < 4; mt++)
#pragma unroll
        for (int nt = 0; nt < 4; nt++)
#pragma unroll
            for (int j = 0; j < 4; j++) acc[mt][nt][j] = 0.f;

    for (int kt = 0; kt < E_NTK; kt++) {
        CP_WAIT1();
        __syncthreads();

        if (kt + 2 < E_NTK) { load_stage(kt + 2, (kt + 2) % 3); CP_COMMIT(); }

        const uint32_t st = sb + 512 + (kt % 3) * E_STAGE;
        const uint32_t aRow = st + (uint32_t)(wm + (lane & 15)) * 128;
        const uint32_t bRowBase = st + E_TILE + (uint32_t)(wn + brow_off) * 128;

#pragma unroll
        for (int kh = 0; kh < 4; kh++) {
            const uint32_t aChunk = (uint32_t)(((kh << 1) | (lane >> 4)) ^ l7) << 4;
            const uint32_t bChunk = (uint32_t)(((kh << 1) | ((lane >> 3) & 1)) ^ l7) << 4;
            uint32_t aF[4][4], bF[2][4];
#pragma unroll
            for (int p = 0; p < 2; p++)
                LDSM4(bF[p], bRowBase + (uint32_t)(p * 16) * 128 + bChunk);
#pragma unroll
            for (int mt = 0; mt < 4; mt++)
                LDSM4(aF[mt], aRow + (uint32_t)(mt * 16) * 128 + aChunk);
#pragma unroll
            for (int mt = 0; mt < 4; mt++)
#pragma unroll
                for (int nt = 0; nt < 4; nt++)
                    mma16816h(acc[mt][nt], aF[mt], &bF[nt >> 1][(nt & 1) * 2]);
        }
    }

    const float* bs = (const float*)smem;
#pragma unroll
    for (int mt = 0; mt < 4; mt++) {
#pragma unroll
        for (int nt = 0; nt < 4; nt++) {
            const int c = wn + nt * 8 + (lane & 3) * 2;
            const size_t r0 = (size_t)bm + wm + mt * 16 + (lane >> 2);
            *(__half2*)&C16[r0 * Nt + bn + c] = __floats2half2_rn(
                acc[mt][nt][0] + bs[c], acc[mt][nt][1] + bs[c + 1]);
            *(__half2*)&C16[(r0 + 8) * Nt + bn + c] = __floats2half2_rn(
                acc[mt][nt][2] + bs[c], acc[mt][nt][3] + bs[c + 1]);
        }
    }
}

// ===========================================================================
// NODE GEMM (fp16, 2-term, SW128 swizzle): C = (Ah + Al) * B16 (+bias).
// BM=64, BN=128, BK=64; grid (Nt/128, 16). Outputs fp32 and/or fp16 hi/lo.
// ===========================================================================
#define M_NTK 16
#define M_ATILE 8192
#define M_BTILE 16384
#define M_STAGE (2 * M_ATILE + M_BTILE)   // 32768
#define M_SM (512 + 3 * M_STAGE)          // 98816

__global__ void __launch_bounds__(256, 1) gemm_f16n(
    const __half* __restrict__ Ah, const __half* __restrict__ Al,
    const __half* __restrict__ BT, const float* __restrict__ bias,
    float* __restrict__ Cf, __half* __restrict__ Ch, __half* __restrict__ Cl,
    int Nt)
{
    extern __shared__ char smem[];
    const uint32_t sb = smem_u32(smem);
    const int tid = threadIdx.x;
    const int wid = tid >> 5;
    const int lane = tid & 31;
    const int bm = blockIdx.y * 64;
    const int bn = blockIdx.x * 128;

    if (tid < 128) ((float*)smem)[tid] = bias ? bias[bn + tid] : 0.f;

    const __half* sAh = Ah + (size_t)bm * GK;
    const __half* sAl = Al + (size_t)bm * GK;
    const __half* sB  = BT + (size_t)bn * GK;

    auto load_stage = [&](int kt, int s) {
        const uint32_t base = sb + 512 + s * M_STAGE;
#pragma unroll
        for (int i = 0; i < 2; i++) {
            const int idx = i * 256 + tid;
            const int row = idx >> 3, c = idx & 7;
            const uint32_t sw = (uint32_t)row * 128 + (uint32_t)((c ^ (row & 7)) << 4);
            CP_ASYNC16(base + sw, sAh + (size_t)row * GK + kt * 64 + c * 8);
            CP_ASYNC16(base + M_ATILE + sw, sAl + (size_t)row * GK + kt * 64 + c * 8);
        }
#pragma unroll
        for (int i = 0; i < 4; i++) {
            const int idx = i * 256 + tid;
            const int row = idx >> 3, c = idx & 7;
            const uint32_t sw = (uint32_t)row * 128 + (uint32_t)((c ^ (row & 7)) << 4);
            CP_ASYNC16(base + 2 * M_ATILE + sw, sB + (size_t)row * GK + kt * 64 + c * 8);
        }
    };

    load_stage(0, 0); CP_COMMIT();
    load_stage(1, 1); CP_COMMIT();

    const int wm = (wid >> 2) * 32;       // 0 or 32
    const int wn = (wid & 3) * 32;        // 0,32,64,96
    const int l7 = lane & 7;
    const int brow_off = l7 + ((lane >> 4) << 3);

    float acc[2][4][4];
#pragma unroll
    for (int mt = 0; mt < 2; mt++)
#pragma unroll
        for (int nt = 0; nt < 4; nt++)
#pragma unroll
            for (int j = 0; j < 4; j++) acc[mt][nt][j] = 0.f;

    for (int kt = 0; kt < M_NTK; kt++) {
        CP_WAIT1();
        __syncthreads();

        if (kt + 2 < M_NTK) { load_stage(kt + 2, (kt + 2) % 3); CP_COMMIT(); }

        const uint32_t st = sb + 512 + (kt % 3) * M_STAGE;
        const uint32_t ahRow = st + (uint32_t)(wm + (lane & 15)) * 128;
        const uint32_t alRow = ahRow + M_ATILE;
        const uint32_t bRowBase = st + 2 * M_ATILE + (uint32_t)(wn + brow_off) * 128;

#pragma unroll
        for (int kh = 0; kh < 4; kh++) {
            const uint32_t aChunk = (uint32_t)(((kh << 1) | (lane >> 4)) ^ l7) << 4;
            const uint32_t bChunk = (uint32_t)(((kh << 1) | ((lane >> 3) & 1)) ^ l7) << 4;
            uint32_t aH[2][4], aL[2][4], bF[2][4];
#pragma unroll
            for (int p = 0; p < 2; p++)
                LDSM4(bF[p], bRowBase + (uint32_t)(p * 16) * 128 + bChunk);
#pragma unroll
            for (int mt = 0; mt < 2; mt++) {
                LDSM4(aH[mt], ahRow + (uint32_t)(mt * 16) * 128 + aChunk);
                LDSM4(aL[mt], alRow + (uint32_t)(mt * 16) * 128 + aChunk);
            }
#pragma unroll
            for (int mt = 0; mt < 2; mt++)
#pragma unroll
                for (int nt = 0; nt < 4; nt++) {
                    const uint32_t* b = &bF[nt >> 1][(nt & 1) * 2];
                    mma16816h(acc[mt][nt], aH[mt], b);
                    mma16816h(acc[mt][nt], aL[mt], b);
                }
        }
    }

    const float* bs = (const float*)smem;
#pragma unroll
    for (int mt = 0; mt < 2; mt++) {
#pragma unroll
        for (int nt = 0; nt < 4; nt++) {
            const int c = wn + nt * 8 + (lane & 3) * 2;
            const size_t r0 = (size_t)bm + wm + mt * 16 + (lane >> 2);
            const float v0 = acc[mt][nt][0] + bs[c];
            const float v1 = acc[mt][nt][1] + bs[c + 1];
            const float v2 = acc[mt][nt][2] + bs[c];
            const float v3 = acc[mt][nt][3] + bs[c + 1];
            if (Cf) {
                *(float2*)&Cf[r0 * Nt + bn + c]       = make_float2(v0, v1);
                *(float2*)&Cf[(r0 + 8) * Nt + bn + c] = make_float2(v2, v3);
            }
            if (Ch) {
                __half2 h01 = __floats2half2_rn(v0, v1);
                __half2 h23 = __floats2half2_rn(v2, v3);
                *(__half2*)&Ch[r0 * Nt + bn + c]       = h01;
                *(__half2*)&Ch[(r0 + 8) * Nt + bn + c] = h23;
                float2 f01 = __half22float2(h01);
                float2 f23 = __half22float2(h23);
                *(__half2*)&Cl[r0 * Nt + bn + c] =
                    __floats2half2_rn(v0 - f01.x, v1 - f01.y);
                *(__half2*)&Cl[(r0 + 8) * Nt + bn + c] =
                    __floats2half2_rn(v2 - f23.x, v3 - f23.y);
            }
        }
    }
}

// ---------------------------------------------------------------------------
// Fused elementwise: edge fp32 -> fp16; node fp32 -> fp16 hi/lo.
// ---------------------------------------------------------------------------
#define EDGE_F4 (N_EDGES * DIM / 4)
#define NODE_F4 (N_NODES * DIM / 4)
#define CONV_BLOCKS (EDGE_F4 / 256 + NODE_F4 / 256)

__global__ void __launch_bounds__(256) fused_conv_kernel(
    const float4* __restrict__ edge, __half2* __restrict__ e16,
    const float4* __restrict__ node, __half2* __restrict__ nh,
    __half2* __restrict__ nl)
{
    const int bid = blockIdx.x;
    if (bid < EDGE_F4 / 256) {
        const int i = bid * 256 + threadIdx.x;
        float4 v = edge[i];
        e16[2 * i + 0] = __floats2half2_rn(v.x, v.y);
        e16[2 * i + 1] = __floats2half2_rn(v.z, v.w);
    } else {
        const int i = (bid - EDGE_F4 / 256) * 256 + threadIdx.x;
        float4 v = node[i];
        __half2 h01 = __floats2half2_rn(v.x, v.y);
        __half2 h23 = __floats2half2_rn(v.z, v.w);
        nh[2 * i + 0] = h01;
        nh[2 * i + 1] = h23;
        float2 f01 = __half22float2(h01);
        float2 f23 = __half22float2(h23);
        nl[2 * i + 0] = __floats2half2_rn(v.x - f01.x, v.y - f01.y);
        nl[2 * i + 1] = __floats2half2_rn(v.z - f23.x, v.w - f23.y);
    }
}

// ---------------------------------------------------------------------------
// Fused weight prep: 5 transpose jobs, all fp16 output. Block (32,8).
// ---------------------------------------------------------------------------
#define WPREP_BLOCKS (1024 * 4 + 128)

__global__ void __launch_bounds__(256) fused_wprep_kernel(
    const float* __restrict__ w_query, const float* __restrict__ w_to_q,
    const float* __restrict__ w_to_k, const float* __restrict__ w_out,
    const float* __restrict__ w_edge,
    __half* __restrict__ wqT16, __half* __restrict__ wqkT16,
    __half* __restrict__ woT16, __half* __restrict__ weT16)
{
    __shared__ float t[32][33];
    int bid = blockIdx.x;
    const float* w; __half* of16;
    int N, nblk;
    if (bid < 1024)      { w = w_query; of16 = wqT16; N = 1024; nblk = bid; }
    else if (bid < 2048) { w = w_to_q;  of16 = wqkT16; N = 1024; nblk = bid - 1024; }
    else if (bid < 2176) { w = w_to_k;  of16 = wqkT16 + (size_t)1024 * 1024;
                           N = 128; nblk = bid - 2048; }
    else if (bid < 3200) { w = w_out;   of16 = woT16; N = 1024; nblk = bid - 2176; }
    else                 { w = w_edge;  of16 = weT16; N = 1024; nblk = bid - 3200; }

    const int nx = N / 32;
    const int n0 = (nblk % nx) * 32, k0 = (nblk / nx) * 32;
    const int tx = threadIdx.x, ty = threadIdx.y;
#pragma unroll
    for (int i = 0; i < 4; i++)
        t[ty + i * 8][tx] = w[(size_t)(k0 + ty + i * 8) * N + n0 + tx];
    __syncthreads();
#pragma unroll
    for (int i = 0; i < 4; i++) {
        const int n = n0 + ty + i * 8, k = k0 + tx;
        of16[(size_t)n * 1024 + k] = __float2half(t[tx][ty + i * 8]);
    }
}

// ---------------------------------------------------------------------------
// kproj[k,d] = sum_n proj_k[n,k] * kv[n,d]  (kv row stride kvs)
// ---------------------------------------------------------------------------
__global__ void __launch_bounds__(128) kproj_kernel(
    const float* __restrict__ kv, int kvs, const float* __restrict__ pk,
    float* __restrict__ kp)
{
    const int k = blockIdx.x;
    const int d = threadIdx.x;
    float s0 = 0.f, s1 = 0.f, s2 = 0.f, s3 = 0.f;
#pragma unroll 4
    for (int n = 0; n < N_NODES; n += 4) {
        s0 += pk[(size_t)(n + 0) * KPROJ + k] * kv[(size_t)(n + 0) * kvs + d];
        s1 += pk[(size_t)(n + 1) * KPROJ + k] * kv[(size_t)(n + 1) * kvs + d];
        s2 += pk[(size_t)(n + 2) * KPROJ + k] * kv[(size_t)(n + 2) * kvs + d];
        s3 += pk[(size_t)(n + 3) * KPROJ + k] * kv[(size_t)(n + 3) * kvs + d];
    }
    kp[(size_t)k * DH + d] = (s0 + s1) + (s2 + s3);
}

// ---------------------------------------------------------------------------
// Attention v3 (interchanged dots loop), output fp16 hi/lo
// ---------------------------------------------------------------------------
#define NPB 4
#define KP_PAD 132
#define ATTN_SMEM ((KPROJ * KP_PAD + NPB * DIM + HEADS * KPROJ * NPB) * 4)

__global__ void __launch_bounds__(256) attn_v3(
    const float* __restrict__ q, int qs, const float* __restrict__ kproj,
    __half* __restrict__ oh, __half* __restrict__ ol)
{
    extern __shared__ float sm[];
    float* kp_s = sm;
    float* q_s  = sm + KPROJ * KP_PAD;
    float* pr_s = q_s + NPB * DIM;

    const int tid = threadIdx.x;
    const int n0 = blockIdx.x * NPB;

    for (int idx = tid; idx < KPROJ * DH; idx += 256) {
        const int r = idx >> 7, c = idx & 127;
        kp_s[r * KP_PAD + c] = kproj[idx];
    }
    for (int idx = tid; idx < NPB * DIM; idx += 256) {
        const int n = idx >> 10, hd = idx & 1023;
        q_s[hd * NPB + n] = q[(size_t)(n0 + n) * qs + hd];
    }
    __syncthreads();

    const int w = tid >> 5;
    const int l = tid & 31;
    const float scale = 0.088388347648318447f;

    float d8[NPB][8];
#pragma unroll
    for (int n = 0; n < NPB; n++)
#pragma unroll
        for (int j = 0; j < 8; j++) d8[n][j] = 0.f;

    const float* qb = q_s + w * DH * NPB;
    const float* krow = kp_s + l * KP_PAD;
    for (int d4 = 0; d4 < DH / 4; d4++) {
        const float4 q0 = *(const float4*)(qb + (d4 * 4 + 0) * NPB);
        const float4 q1 = *(const float4*)(qb + (d4 * 4 + 1) * NPB);
        const float4 q2 = *(const float4*)(qb + (d4 * 4 + 2) * NPB);
        const float4 q3 = *(const float4*)(qb + (d4 * 4 + 3) * NPB);
#pragma unroll
        for (int j = 0; j < 8; j++) {
            const float4 kk = *(const float4*)(krow + j * 32 * KP_PAD + d4 * 4);
            d8[0][j] += kk.x * q0.x + kk.y * q1.x + kk.z * q2.x + kk.w * q3.x;
            d8[1][j] += kk.x * q0.y + kk.y * q1.y + kk.z * q2.y + kk.w * q3.y;
            d8[2][j] += kk.x * q0.z + kk.y * q1.z + kk.z * q2.z + kk.w * q3.z;
            d8[3][j] += kk.x * q0.w + kk.y * q1.w + kk.z * q2.w + kk.w * q3.w;
        }
    }

#pragma unroll
    for (int n = 0; n < NPB; n++) {
        float mx = d8[n][0] * scale;
#pragma unroll
        for (int j = 0; j < 8; j++) { d8[n][j] *= scale; mx = fmaxf(mx, d8[n][j]); }
#pragma unroll
        for (int o = 16; o; o >>= 1) mx = fmaxf(mx, __shfl_xor_sync(0xFFFFFFFFu, mx, o));
        float sum = 0.f;
#pragma unroll
        for (int j = 0; j < 8; j++) { d8[n][j] = expf(d8[n][j] - mx); sum += d8[n][j]; }
#pragma unroll
        for (int o = 16; o; o >>= 1) sum += __shfl_xor_sync(0xFFFFFFFFu, sum, o);
        const float inv = 1.f / sum;
#pragma unroll
        for (int j = 0; j < 8; j++)
            pr_s[(w * KPROJ + j * 32 + l) * NPB + n] = d8[n][j] * inv;
    }
    __syncwarp();

    float4 o4[NPB];
#pragma unroll
    for (int n = 0; n < NPB; n++) o4[n] = make_float4(0.f, 0.f, 0.f, 0.f);
    const float* prb = pr_s + w * KPROJ * NPB;
#pragma unroll 4
    for (int k = 0; k < KPROJ; k++) {
        const float4 kk = *(const float4*)(kp_s + k * KP_PAD + l * 4);
        const float4 pp = *(const float4*)(prb + k * NPB);
        o4[0].x += pp.x * kk.x; o4[0].y += pp.x * kk.y;
        o4[0].z += pp.x * kk.z; o4[0].w += pp.x * kk.w;
        o4[1].x += pp.y * kk.x; o4[1].y += pp.y * kk.y;
        o4[1].z += pp.y * kk.z; o4[1].w += pp.y * kk.w;
        o4[2].x += pp.z * kk.x; o4[2].y += pp.z * kk.y;
        o4[2].z += pp.z * kk.z; o4[2].w += pp.z * kk.w;
        o4[3].x += pp.w * kk.x; o4[3].y += pp.w * kk.y;
        o4[3].z += pp.w * kk.z; o4[3].w += pp.w * kk.w;
    }

#pragma unroll
    for (int n = 0; n < NPB; n++) {
        const size_t ob = (size_t)(n0 + n) * DIM + w * DH + l * 4;
        __half2 h01 = __floats2half2_rn(o4[n].x, o4[n].y);
        __half2 h23 = __floats2half2_rn(o4[n].z, o4[n].w);
        *(__half2*)&oh[ob]     = h01;
        *(__half2*)&oh[ob + 2] = h23;
        float2 f01 = __half22float2(h01);
        float2 f23 = __half22float2(h23);
        *(__half2*)&ol[ob]     = __floats2half2_rn(o4[n].x - f01.x, o4[n].y - f01.y);
        *(__half2*)&ol[ob + 2] = __floats2half2_rn(o4[n].z - f23.x, o4[n].w - f23.y);
    }
}

// ---------------------------------------------------------------------------
// LayerNorm + residual, fp32 src (node path)
// ---------------------------------------------------------------------------
__global__ void __launch_bounds__(256) ln_res_kernel(
    const float* __restrict__ src, const float* __restrict__ resid,
    const float* __restrict__ gamma, const float* __restrict__ beta,
    float* __restrict__ dst)
{
    const int row = blockIdx.x;
    const int t = threadIdx.x;
    const float4 v = *(const float4*)&src[(size_t)row * DIM + t * 4];

    float sum = v.x + v.y + v.z + v.w;
    float sq = v.x * v.x + v.y * v.y + v.z * v.z + v.w * v.w;
#pragma unroll
    for (int o = 16; o; o >>= 1) {
        sum += __shfl_xor_sync(0xFFFFFFFFu, sum, o);
        sq  += __shfl_xor_sync(0xFFFFFFFFu, sq, o);
    }
    __shared__ float ssum[8], ssq[8];
    const int w = t >> 5, l = t & 31;
    if (l == 0) { ssum[w] = sum; ssq[w] = sq; }
    __syncthreads();
    sum = 0.f; sq = 0.f;
#pragma unroll
    for (int i = 0; i < 8; i++) { sum += ssum[i]; sq += ssq[i]; }

    const float mu = sum * (1.f / DIM);
    const float var = sq * (1.f / DIM) - mu * mu;
    const float rstd = rsqrtf(var + 1e-5f);

    const float4 g = *(const float4*)&gamma[t * 4];
    const float4 b = *(const float4*)&beta[t * 4];
    const float4 rr = *(const float4*)&resid[(size_t)row * DIM + t * 4];
    float4 o;
    o.x = (v.x - mu) * rstd * g.x + b.x + rr.x;
    o.y = (v.y - mu) * rstd * g.y + b.y + rr.y;
    o.z = (v.z - mu) * rstd * g.z + b.z + rr.z;
    o.w = (v.w - mu) * rstd * g.w + b.w + rr.w;
    *(float4*)&dst[(size_t)row * DIM + t * 4] = o;
}

// ---------------------------------------------------------------------------
// LayerNorm + residual, fp16 src (edge path) -> fp32 out
// ---------------------------------------------------------------------------
__global__ void __launch_bounds__(256) ln_res_h_kernel(
    const __half* __restrict__ src, const float* __restrict__ resid,
    const float* __restrict__ gamma, const float* __restrict__ beta,
    float* __restrict__ dst)
{
    const int row = blockIdx.x;
    const int t = threadIdx.x;
    const __half2 h01 = *(const __half2*)&src[(size_t)row * DIM + t * 4];
    const __half2 h23 = *(const __half2*)&src[(size_t)row * DIM + t * 4 + 2];
    const float2 f01 = __half22float2(h01);
    const float2 f23 = __half22float2(h23);
    float4 v = make_float4(f01.x, f01.y, f23.x, f23.y);

    float sum = v.x + v.y + v.z + v.w;
    float sq = v.x * v.x + v.y * v.y + v.z * v.z + v.w * v.w;
#pragma unroll
    for (int o = 16; o; o >>= 1) {
        sum += __shfl_xor_sync(0xFFFFFFFFu, sum, o);
        sq  += __shfl_xor_sync(0xFFFFFFFFu, sq, o);
    }
    __shared__ float ssum[8], ssq[8];
    const int w = t >> 5, l = t & 31;
    if (l == 0) { ssum[w] = sum; ssq[w] = sq; }
    __syncthreads();
    sum = 0.f; sq = 0.f;
#pragma unroll
    for (int i = 0; i < 8; i++) { sum += ssum[i]; sq += ssq[i]; }

    const float mu = sum * (1.f / DIM);
    const float var = sq * (1.f / DIM) - mu * mu;
    const float rstd = rsqrtf(var + 1e-5f);

    const float4 g = *(const float4*)&gamma[t * 4];
    const float4 b = *(const float4*)&beta[t * 4];
    const float4 rr = *(const float4*)&resid[(size_t)row * DIM + t * 4];
    float4 o;
    o.x = (v.x - mu) * rstd * g.x + b.x + rr.x;
    o.y = (v.y - mu) * rstd * g.y + b.y + rr.y;
    o.z = (v.z - mu) * rstd * g.z + b.z + rr.z;
    o.w = (v.w - mu) * rstd * g.w + b.w + rr.w;
    *(float4*)&dst[(size_t)row * DIM + t * 4] = o;
}

// ---------------------------------------------------------------------------
// kernel_launch (single stream)
// ---------------------------------------------------------------------------
extern "C" void kernel_launch(void* const* d_in, const int* in_sizes, int n_in,
                              void* d_out, int out_size)
{
    const float* node       = (const float*)d_in[0];
    const float* edge       = (const float*)d_in[1];
    const float* w_query    = (const float*)d_in[2];
    const float* b_query    = (const float*)d_in[3];
    const float* w_edge     = (const float*)d_in[4];
    const float* b_edge     = (const float*)d_in[5];
    const float* w_to_q     = (const float*)d_in[6];
    const float* w_to_k     = (const float*)d_in[7];
    const float* proj_k     = (const float*)d_in[8];
    const float* w_out      = (const float*)d_in[9];
    const float* b_out      = (const float*)d_in[10];
    const float* gamma_node = (const float*)d_in[11];
    const float* beta_node  = (const float*)d_in[12];
    const float* gamma_edge = (const float*)d_in[13];
    const float* beta_edge  = (const float*)d_in[14];

    float* x_out = (float*)d_out;
    float* y_out = (float*)d_out + (size_t)N_NODES * DIM;

    __half *e16, *y16, *weT16, *nh16, *nl16, *wqT16, *wqkT16, *woT16;
    __half *xqh16, *xql16, *ah16, *al16;
    float *qkv, *kp, *xattn;
    cudaGetSymbolAddress((void**)&e16, g_e16);
    cudaGetSymbolAddress((void**)&y16, g_y16);
    cudaGetSymbolAddress((void**)&weT16, g_weT16);
    cudaGetSymbolAddress((void**)&nh16, g_nh16);
    cudaGetSymbolAddress((void**)&nl16, g_nl16);
    cudaGetSymbolAddress((void**)&wqT16, g_wqT16);
    cudaGetSymbolAddress((void**)&wqkT16, g_wqkT16);
    cudaGetSymbolAddress((void**)&woT16, g_woT16);
    cudaGetSymbolAddress((void**)&xqh16, g_xqh16);
    cudaGetSymbolAddress((void**)&xql16, g_xql16);
    cudaGetSymbolAddress((void**)&ah16, g_ah16);
    cudaGetSymbolAddress((void**)&al16, g_al16);
    cudaGetSymbolAddress((void**)&qkv, g_qkv);
    cudaGetSymbolAddress((void**)&kp, g_kproj);
    cudaGetSymbolAddress((void**)&xattn, g_xattn);

    static bool attr_set = false;
    if (!attr_set) {
        cudaFuncSetAttribute(gemm_f16n,
                             cudaFuncAttributeMaxDynamicSharedMemorySize, M_SM);
        cudaFuncSetAttribute(gemm_f16_sw,
                             cudaFuncAttributeMaxDynamicSharedMemorySize, E_SM);
        cudaFuncSetAttribute(attn_v3,
                             cudaFuncAttributeMaxDynamicSharedMemorySize, ATTN_SMEM);
        attr_set = true;
    }

    // 1. fused elementwise converts
    fused_conv_kernel<<<CONV_BLOCKS, 256>>>(
        (const float4*)edge, (__half2*)e16,
        (const float4*)node, (__half2*)nh16, (__half2*)nl16);
    // 2. fused weight prep (all fp16)
    fused_wprep_kernel<<<WPREP_BLOCKS, dim3(32, 8)>>>(
        w_query, w_to_q, w_to_k, w_out, w_edge,
        wqT16, wqkT16, woT16, weT16);
    // 3. node GEMM #1 (xq -> fp16 hi/lo)
    gemm_f16n<<<dim3(8, 16), 256, M_SM>>>(
        nh16, nl16, wqT16, b_query, nullptr, xqh16, xql16, DIM);
    // 4. edge GEMM -> fp16 intermediate (profiled slot)
    gemm_f16_sw<<<dim3(8, 256), 256, E_SM>>>(e16, weT16, b_edge, y16, DIM);
    // 5. edge LN (fp16 src -> fp32 out)
    ln_res_h_kernel<<<N_EDGES, 256>>>(y16, edge, gamma_edge, beta_edge, y_out);
    // 6. node GEMM #2 (qkv fp32)
    gemm_f16n<<<dim3(9, 16), 256, M_SM>>>(
        xqh16, xql16, wqkT16, nullptr, qkv, nullptr, nullptr, QKV_N);
    // 7-8. kproj + attention
    kproj_kernel<<<KPROJ, 128>>>(qkv + 1024, QKV_N, proj_k, kp);
    attn_v3<<<N_NODES / NPB, 256, ATTN_SMEM>>>(qkv, QKV_N, kp, ah16, al16);
    // 9. node GEMM #3 (x_attn fp32)
    gemm_f16n<<<dim3(8, 16), 256, M_SM>>>(
        ah16, al16, woT16, b_out, xattn, nullptr, nullptr, DIM);
    // 10. node LN
    ln_res_kernel<<<N_NODES, 256>>>(xattn, node, gamma_node, beta_node, x_out);
}

// round 16
// speedup vs baseline: 1.4145x; 1.0046x over previous
#include <cuda_runtime.h>
#include <cuda_bf16.h>
#include <cuda_fp16.h>
#include <math.h>
#include <stdint.h>

#define N_NODES 1024
#define N_EDGES 32768
#define DIM     1024
#define HEADS   8
#define DH      128
#define KPROJ   256
#define QKV_N   1152   // w_to_q (1024) ++ w_to_k (128), fused GEMM

// ---------------------------------------------------------------------------
// Scratch (device globals -- no allocation allowed)
// ---------------------------------------------------------------------------
__device__ __half g_e16[N_EDGES * DIM];                      // edge fp16
__device__ __half g_y16[N_EDGES * DIM];                      // edge GEMM out fp16
__device__ __half g_weT16[DIM * DIM];                        // w_edge^T fp16
__device__ __half g_nh16[N_NODES * DIM], g_nl16[N_NODES * DIM]; // node fp16 hi/lo
__device__ __half g_wqT16[DIM * DIM];                        // w_query^T fp16
__device__ __half g_wqkT16[QKV_N * DIM];                     // [w_to_q|w_to_k]^T fp16
__device__ __half g_woT16[DIM * DIM];                        // w_out^T fp16
__device__ __half g_xqh16[N_NODES * DIM], g_xql16[N_NODES * DIM]; // xq fp16 hi/lo
__device__ float  g_qkv[N_NODES * QKV_N];                    // [q | kv] fp32
__device__ float  g_kproj[KPROJ * DH];
__device__ __half g_ah16[N_NODES * DIM], g_al16[N_NODES * DIM];  // attn out fp16 hi/lo
__device__ float  g_xattn[N_NODES * DIM];

// ---------------------------------------------------------------------------
// Generic-ISA PTX helpers
// ---------------------------------------------------------------------------
__device__ __forceinline__ uint32_t smem_u32(const void* p) {
    uint32_t a;
    asm("{ .reg .u64 t; cvta.to.shared.u64 t, %1; cvt.u32.u64 %0, t; }"
        : "=r"(a) : "l"(p));
    return a;
}

#define CP_ASYNC16(dst, src) \
    asm volatile("cp.async.cg.shared.global [%0], [%1], 16;" :: "r"(dst), "l"(src))
#define CP_COMMIT() asm volatile("cp.async.commit_group;" ::: "memory")
#define CP_WAIT1()  asm volatile("cp.async.wait_group 1;" ::: "memory")

#define LDSM4(r, addr) \
    asm volatile("ldmatrix.sync.aligned.m8n8.x4.shared.b16 {%0,%1,%2,%3}, [%4];" \
        : "=r"((r)[0]), "=r"((r)[1]), "=r"((r)[2]), "=r"((r)[3]) : "r"(addr))

__device__ __forceinline__ void mma16816h(float* c, const uint32_t* a, const uint32_t* b) {
    asm volatile(
        "mma.sync.aligned.m16n8k16.row.col.f32.f16.f16.f32 "
        "{%0,%1,%2,%3}, {%4,%5,%6,%7}, {%8,%9}, {%0,%1,%2,%3};"
        : "+f"(c[0]), "+f"(c[1]), "+f"(c[2]), "+f"(c[3])
        : "r"(a[0]), "r"(a[1]), "r"(a[2]), "r"(a[3]), "r"(b[0]), "r"(b[1]));
}

#define GK 1024

// ===========================================================================
// EDGE GEMM (fp16, 1-term, SW128 swizzle). Output fp16. Unchanged (proven).
// ===========================================================================
#define E_NTK 16
#define E_TILE 16384
#define E_STAGE (2 * E_TILE)
#define E_SM (512 + 3 * E_STAGE)

__global__ void __launch_bounds__(256, 2) gemm_f16_sw(
    const __half* __restrict__ A16, const __half* __restrict__ BhT,
    const float* __restrict__ bias, __half* __restrict__ C16, int Nt)
{
    extern __shared__ char smem[];
    const uint32_t sb = smem_u32(smem);
    const int tid = threadIdx.x;
    const int wid = tid >> 5;
    const int lane = tid & 31;
    const int bm = blockIdx.y * 128;
    const int bn = blockIdx.x * 128;

    if (tid < 128) ((float*)smem)[tid] = bias ? bias[bn + tid] : 0.f;

    const __half* srcA = A16 + (size_t)bm * GK;
    const __half* srcB = BhT + (size_t)bn * GK;

    auto load_stage = [&](int kt, int s) {
        const uint32_t base = sb + 512 + s * E_STAGE;
#pragma unroll
        for (int i = 0; i < 4; i++) {
            const int idx = i * 256 + tid;
            const int row = idx >> 3, c = idx & 7;
            const uint32_t sw = (uint32_t)row * 128 + (uint32_t)((c ^ (row & 7)) << 4);
            CP_ASYNC16(base + sw, srcA + (size_t)row * GK + kt * 64 + c * 8);
        }
#pragma unroll
        for (int i = 0; i < 4; i++) {
            const int idx = i * 256 + tid;
            const int row = idx >> 3, c = idx & 7;
            const uint32_t sw = (uint32_t)row * 128 + (uint32_t)((c ^ (row & 7)) << 4);
            CP_ASYNC16(base + E_TILE + sw, srcB + (size_t)row * GK + kt * 64 + c * 8);
        }
    };

    load_stage(0, 0); CP_COMMIT();
    load_stage(1, 1); CP_COMMIT();

    const int wm = (wid >> 2) * 64;
    const int wn = (wid & 3) * 32;
    const int l7 = lane & 7;
    const int brow_off = l7 + ((lane >> 4) << 3);

    float acc[4][4][4];
#pragma unroll
    for (int mt = 0; mt < 4; mt++)
#pragma unroll
        for (int nt = 0; nt < 4; nt++)
#pragma unroll
            for (int j = 0; j < 4; j++) acc[mt][nt][j] = 0.f;

    for (int kt = 0; kt < E_NTK; kt++) {
        CP_WAIT1();
        __syncthreads();

        if (kt + 2 < E_NTK) { load_stage(kt + 2, (kt + 2) % 3); CP_COMMIT(); }

        const uint32_t st = sb + 512 + (kt % 3) * E_STAGE;
        const uint32_t aRow = st + (uint32_t)(wm + (lane & 15)) * 128;
        const uint32_t bRowBase = st + E_TILE + (uint32_t)(wn + brow_off) * 128;

#pragma unroll
        for (int kh = 0; kh < 4; kh++) {
            const uint32_t aChunk = (uint32_t)(((kh << 1) | (lane >> 4)) ^ l7) << 4;
            const uint32_t bChunk = (uint32_t)(((kh << 1) | ((lane >> 3) & 1)) ^ l7) << 4;
            uint32_t aF[4][4], bF[2][4];
#pragma unroll
            for (int p = 0; p < 2; p++)
                LDSM4(bF[p], bRowBase + (uint32_t)(p * 16) * 128 + bChunk);
#pragma unroll
            for (int mt = 0; mt < 4; mt++)
                LDSM4(aF[mt], aRow + (uint32_t)(mt * 16) * 128 + aChunk);
#pragma unroll
            for (int mt = 0; mt < 4; mt++)
#pragma unroll
                for (int nt = 0; nt < 4; nt++)
                    mma16816h(acc[mt][nt], aF[mt], &bF[nt >> 1][(nt & 1) * 2]);
        }
    }

    const float* bs = (const float*)smem;
#pragma unroll
    for (int mt = 0; mt < 4; mt++) {
#pragma unroll
        for (int nt = 0; nt < 4; nt++) {
            const int c = wn + nt * 8 + (lane & 3) * 2;
            const size_t r0 = (size_t)bm + wm + mt * 16 + (lane >> 2);
            *(__half2*)&C16[r0 * Nt + bn + c] = __floats2half2_rn(
                acc[mt][nt][0] + bs[c], acc[mt][nt][1] + bs[c + 1]);
            *(__half2*)&C16[(r0 + 8) * Nt + bn + c] = __floats2half2_rn(
                acc[mt][nt][2] + bs[c], acc[mt][nt][3] + bs[c + 1]);
        }
    }
}

// ===========================================================================
// NODE GEMM (fp16, 2-term): C = (Ah + Al) * B16 (+bias).
// BM=32, BN=128, BK=64; grid (Nt/128, 32) -> 256+ CTAs, 2 CTAs/SM.
// ===========================================================================
#define M_NTK 16
#define M_ATILE 4096                      // 32 rows x 128 B
#define M_BTILE 16384
#define M_STAGE (2 * M_ATILE + M_BTILE)   // 24576
#define M_SM (512 + 3 * M_STAGE)          // 74240

__global__ void __launch_bounds__(256, 2) gemm_f16n(
    const __half* __restrict__ Ah, const __half* __restrict__ Al,
    const __half* __restrict__ BT, const float* __restrict__ bias,
    float* __restrict__ Cf, __half* __restrict__ Ch, __half* __restrict__ Cl,
    int Nt)
{
    extern __shared__ char smem[];
    const uint32_t sb = smem_u32(smem);
    const int tid = threadIdx.x;
    const int wid = tid >> 5;
    const int lane = tid & 31;
    const int bm = blockIdx.y * 32;
    const int bn = blockIdx.x * 128;

    if (tid < 128) ((float*)smem)[tid] = bias ? bias[bn + tid] : 0.f;

    const __half* sAh = Ah + (size_t)bm * GK;
    const __half* sAl = Al + (size_t)bm * GK;
    const __half* sB  = BT + (size_t)bn * GK;

    auto load_stage = [&](int kt, int s) {
        const uint32_t base = sb + 512 + s * M_STAGE;
        {   // A tiles: 32 rows x 8 chunks = 256 chunks each, 1 per thread
            const int row = tid >> 3, c = tid & 7;
            const uint32_t sw = (uint32_t)row * 128 + (uint32_t)((c ^ (row & 7)) << 4);
            CP_ASYNC16(base + sw, sAh + (size_t)row * GK + kt * 64 + c * 8);
            CP_ASYNC16(base + M_ATILE + sw, sAl + (size_t)row * GK + kt * 64 + c * 8);
        }
#pragma unroll
        for (int i = 0; i < 4; i++) {
            const int idx = i * 256 + tid;
            const int row = idx >> 3, c = idx & 7;
            const uint32_t sw = (uint32_t)row * 128 + (uint32_t)((c ^ (row & 7)) << 4);
            CP_ASYNC16(base + 2 * M_ATILE + sw, sB + (size_t)row * GK + kt * 64 + c * 8);
        }
    };

    load_stage(0, 0); CP_COMMIT();
    load_stage(1, 1); CP_COMMIT();

    const int wm = (wid >> 2) * 16;       // 0 or 16
    const int wn = (wid & 3) * 32;        // 0,32,64,96
    const int l7 = lane & 7;
    const int brow_off = l7 + ((lane >> 4) << 3);

    float acc[4][4];
#pragma unroll
    for (int nt = 0; nt < 4; nt++)
#pragma unroll
        for (int j = 0; j < 4; j++) acc[nt][j] = 0.f;

    for (int kt = 0; kt < M_NTK; kt++) {
        CP_WAIT1();
        __syncthreads();

        if (kt + 2 < M_NTK) { load_stage(kt + 2, (kt + 2) % 3); CP_COMMIT(); }

        const uint32_t st = sb + 512 + (kt % 3) * M_STAGE;
        const uint32_t ahRow = st + (uint32_t)(wm + (lane & 15)) * 128;
        const uint32_t alRow = ahRow + M_ATILE;
        const uint32_t bRowBase = st + 2 * M_ATILE + (uint32_t)(wn + brow_off) * 128;

#pragma unroll
        for (int kh = 0; kh < 4; kh++) {
            const uint32_t aChunk = (uint32_t)(((kh << 1) | (lane >> 4)) ^ l7) << 4;
            const uint32_t bChunk = (uint32_t)(((kh << 1) | ((lane >> 3) & 1)) ^ l7) << 4;
            uint32_t aH[4], aL[4], bF[2][4];
#pragma unroll
            for (int p = 0; p < 2; p++)
                LDSM4(bF[p], bRowBase + (uint32_t)(p * 16) * 128 + bChunk);
            LDSM4(aH, ahRow + aChunk);
            LDSM4(aL, alRow + aChunk);
#pragma unroll
            for (int nt = 0; nt < 4; nt++) {
                const uint32_t* b = &bF[nt >> 1][(nt & 1) * 2];
                mma16816h(acc[nt], aH, b);
                mma16816h(acc[nt], aL, b);
            }
        }
    }

    const float* bs = (const float*)smem;
#pragma unroll
    for (int nt = 0; nt < 4; nt++) {
        const int c = wn + nt * 8 + (lane & 3) * 2;
        const size_t r0 = (size_t)bm + wm + (lane >> 2);
        const float v0 = acc[nt][0] + bs[c];
        const float v1 = acc[nt][1] + bs[c + 1];
        const float v2 = acc[nt][2] + bs[c];
        const float v3 = acc[nt][3] + bs[c + 1];
        if (Cf) {
            *(float2*)&Cf[r0 * Nt + bn + c]       = make_float2(v0, v1);
            *(float2*)&Cf[(r0 + 8) * Nt + bn + c] = make_float2(v2, v3);
        }
        if (Ch) {
            __half2 h01 = __floats2half2_rn(v0, v1);
            __half2 h23 = __floats2half2_rn(v2, v3);
            *(__half2*)&Ch[r0 * Nt + bn + c]       = h01;
            *(__half2*)&Ch[(r0 + 8) * Nt + bn + c] = h23;
            float2 f01 = __half22float2(h01);
            float2 f23 = __half22float2(h23);
            *(__half2*)&Cl[r0 * Nt + bn + c] =
                __floats2half2_rn(v0 - f01.x, v1 - f01.y);
            *(__half2*)&Cl[(r0 + 8) * Nt + bn + c] =
                __floats2half2_rn(v2 - f23.x, v3 - f23.y);
        }
    }
}

// ---------------------------------------------------------------------------
// Fused elementwise: edge fp32 -> fp16; node fp32 -> fp16 hi/lo.
// ---------------------------------------------------------------------------
#define EDGE_F4 (N_EDGES * DIM / 4)
#define NODE_F4 (N_NODES * DIM / 4)
#define CONV_BLOCKS (EDGE_F4 / 256 + NODE_F4 / 256)

__global__ void __launch_bounds__(256) fused_conv_kernel(
    const float4* __restrict__ edge, __half2* __restrict__ e16,
    const float4* __restrict__ node, __half2* __restrict__ nh,
    __half2* __restrict__ nl)
{
    const int bid = blockIdx.x;
    if (bid < EDGE_F4 / 256) {
        const int i = bid * 256 + threadIdx.x;
        float4 v = edge[i];
        e16[2 * i + 0] = __floats2half2_rn(v.x, v.y);
        e16[2 * i + 1] = __floats2half2_rn(v.z, v.w);
    } else {
        const int i = (bid - EDGE_F4 / 256) * 256 + threadIdx.x;
        float4 v = node[i];
        __half2 h01 = __floats2half2_rn(v.x, v.y);
        __half2 h23 = __floats2half2_rn(v.z, v.w);
        nh[2 * i + 0] = h01;
        nh[2 * i + 1] = h23;
        float2 f01 = __half22float2(h01);
        float2 f23 = __half22float2(h23);
        nl[2 * i + 0] = __floats2half2_rn(v.x - f01.x, v.y - f01.y);
        nl[2 * i + 1] = __floats2half2_rn(v.z - f23.x, v.w - f23.y);
    }
}

// ---------------------------------------------------------------------------
// Fused weight prep: 5 transpose jobs, all fp16 output. Block (32,8).
// ---------------------------------------------------------------------------
#define WPREP_BLOCKS (1024 * 4 + 128)

__global__ void __launch_bounds__(256) fused_wprep_kernel(
    const float* __restrict__ w_query, const float* __restrict__ w_to_q,
    const float* __restrict__ w_to_k, const float* __restrict__ w_out,
    const float* __restrict__ w_edge,
    __half* __restrict__ wqT16, __half* __restrict__ wqkT16,
    __half* __restrict__ woT16, __half* __restrict__ weT16)
{
    __shared__ float t[32][33];
    int bid = blockIdx.x;
    const float* w; __half* of16;
    int N, nblk;
    if (bid < 1024)      { w = w_query; of16 = wqT16; N = 1024; nblk = bid; }
    else if (bid < 2048) { w = w_to_q;  of16 = wqkT16; N = 1024; nblk = bid - 1024; }
    else if (bid < 2176) { w = w_to_k;  of16 = wqkT16 + (size_t)1024 * 1024;
                           N = 128; nblk = bid - 2048; }
    else if (bid < 3200) { w = w_out;   of16 = woT16; N = 1024; nblk = bid - 2176; }
    else                 { w = w_edge;  of16 = weT16; N = 1024; nblk = bid - 3200; }

    const int nx = N / 32;
    const int n0 = (nblk % nx) * 32, k0 = (nblk / nx) * 32;
    const int tx = threadIdx.x, ty = threadIdx.y;
#pragma unroll
    for (int i = 0; i < 4; i++)
        t[ty + i * 8][tx] = w[(size_t)(k0 + ty + i * 8) * N + n0 + tx];
    __syncthreads();
#pragma unroll
    for (int i = 0; i < 4; i++) {
        const int n = n0 + ty + i * 8, k = k0 + tx;
        of16[(size_t)n * 1024 + k] = __float2half(t[tx][ty + i * 8]);
    }
}

// ---------------------------------------------------------------------------
// kproj[k,d] = sum_n proj_k[n,k] * kv[n,d]  (kv row stride kvs)
// ---------------------------------------------------------------------------
__global__ void __launch_bounds__(128) kproj_kernel(
    const float* __restrict__ kv, int kvs, const float* __restrict__ pk,
    float* __restrict__ kp)
{
    const int k = blockIdx.x;
    const int d = threadIdx.x;
    float s0 = 0.f, s1 = 0.f, s2 = 0.f, s3 = 0.f;
#pragma unroll 4
    for (int n = 0; n < N_NODES; n += 4) {
        s0 += pk[(size_t)(n + 0) * KPROJ + k] * kv[(size_t)(n + 0) * kvs + d];
        s1 += pk[(size_t)(n + 1) * KPROJ + k] * kv[(size_t)(n + 1) * kvs + d];
        s2 += pk[(size_t)(n + 2) * KPROJ + k] * kv[(size_t)(n + 2) * kvs + d];
        s3 += pk[(size_t)(n + 3) * KPROJ + k] * kv[(size_t)(n + 3) * kvs + d];
    }
    kp[(size_t)k * DH + d] = (s0 + s1) + (s2 + s3);
}

// ---------------------------------------------------------------------------
// Attention v3 (interchanged dots loop), output fp16 hi/lo -- unchanged
// ---------------------------------------------------------------------------
#define NPB 4
#define KP_PAD 132
#define ATTN_SMEM ((KPROJ * KP_PAD + NPB * DIM + HEADS * KPROJ * NPB) * 4)

__global__ void __launch_bounds__(256) attn_v3(
    const float* __restrict__ q, int qs, const float* __restrict__ kproj,
    __half* __restrict__ oh, __half* __restrict__ ol)
{
    extern __shared__ float sm[];
    float* kp_s = sm;
    float* q_s  = sm + KPROJ * KP_PAD;
    float* pr_s = q_s + NPB * DIM;

    const int tid = threadIdx.x;
    const int n0 = blockIdx.x * NPB;

    for (int idx = tid; idx < KPROJ * DH; idx += 256) {
        const int r = idx >> 7, c = idx & 127;
        kp_s[r * KP_PAD + c] = kproj[idx];
    }
    for (int idx = tid; idx < NPB * DIM; idx += 256) {
        const int n = idx >> 10, hd = idx & 1023;
        q_s[hd * NPB + n] = q[(size_t)(n0 + n) * qs + hd];
    }
    __syncthreads();

    const int w = tid >> 5;
    const int l = tid & 31;
    const float scale = 0.088388347648318447f;

    float d8[NPB][8];
#pragma unroll
    for (int n = 0; n < NPB; n++)
#pragma unroll
        for (int j = 0; j < 8; j++) d8[n][j] = 0.f;

    const float* qb = q_s + w * DH * NPB;
    const float* krow = kp_s + l * KP_PAD;
    for (int d4 = 0; d4 < DH / 4; d4++) {
        const float4 q0 = *(const float4*)(qb + (d4 * 4 + 0) * NPB);
        const float4 q1 = *(const float4*)(qb + (d4 * 4 + 1) * NPB);
        const float4 q2 = *(const float4*)(qb + (d4 * 4 + 2) * NPB);
        const float4 q3 = *(const float4*)(qb + (d4 * 4 + 3) * NPB);
#pragma unroll
        for (int j = 0; j < 8; j++) {
            const float4 kk = *(const float4*)(krow + j * 32 * KP_PAD + d4 * 4);
            d8[0][j] += kk.x * q0.x + kk.y * q1.x + kk.z * q2.x + kk.w * q3.x;
            d8[1][j] += kk.x * q0.y + kk.y * q1.y + kk.z * q2.y + kk.w * q3.y;
            d8[2][j] += kk.x * q0.z + kk.y * q1.z + kk.z * q2.z + kk.w * q3.z;
            d8[3][j] += kk.x * q0.w + kk.y * q1.w + kk.z * q2.w + kk.w * q3.w;
        }
    }

#pragma unroll
    for (int n = 0; n < NPB; n++) {
        float mx = d8[n][0] * scale;
#pragma unroll
        for (int j = 0; j < 8; j++) { d8[n][j] *= scale; mx = fmaxf(mx, d8[n][j]); }
#pragma unroll
        for (int o = 16; o; o >>= 1) mx = fmaxf(mx, __shfl_xor_sync(0xFFFFFFFFu, mx, o));
        float sum = 0.f;
#pragma unroll
        for (int j = 0; j < 8; j++) { d8[n][j] = expf(d8[n][j] - mx); sum += d8[n][j]; }
#pragma unroll
        for (int o = 16; o; o >>= 1) sum += __shfl_xor_sync(0xFFFFFFFFu, sum, o);
        const float inv = 1.f / sum;
#pragma unroll
        for (int j = 0; j < 8; j++)
            pr_s[(w * KPROJ + j * 32 + l) * NPB + n] = d8[n][j] * inv;
    }
    __syncwarp();

    float4 o4[NPB];
#pragma unroll
    for (int n = 0; n < NPB; n++) o4[n] = make_float4(0.f, 0.f, 0.f, 0.f);
    const float* prb = pr_s + w * KPROJ * NPB;
#pragma unroll 4
    for (int k = 0; k < KPROJ; k++) {
        const float4 kk = *(const float4*)(kp_s + k * KP_PAD + l * 4);
        const float4 pp = *(const float4*)(prb + k * NPB);
        o4[0].x += pp.x * kk.x; o4[0].y += pp.x * kk.y;
        o4[0].z += pp.x * kk.z; o4[0].w += pp.x * kk.w;
        o4[1].x += pp.y * kk.x; o4[1].y += pp.y * kk.y;
        o4[1].z += pp.y * kk.z; o4[1].w += pp.y * kk.w;
        o4[2].x += pp.z * kk.x; o4[2].y += pp.z * kk.y;
        o4[2].z += pp.z * kk.z; o4[2].w += pp.z * kk.w;
        o4[3].x += pp.w * kk.x; o4[3].y += pp.w * kk.y;
        o4[3].z += pp.w * kk.z; o4[3].w += pp.w * kk.w;
    }

#pragma unroll
    for (int n = 0; n < NPB; n++) {
        const size_t ob = (size_t)(n0 + n) * DIM + w * DH + l * 4;
        __half2 h01 = __floats2half2_rn(o4[n].x, o4[n].y);
        __half2 h23 = __floats2half2_rn(o4[n].z, o4[n].w);
        *(__half2*)&oh[ob]     = h01;
        *(__half2*)&oh[ob + 2] = h23;
        float2 f01 = __half22float2(h01);
        float2 f23 = __half22float2(h23);
        *(__half2*)&ol[ob]     = __floats2half2_rn(o4[n].x - f01.x, o4[n].y - f01.y);
        *(__half2*)&ol[ob + 2] = __floats2half2_rn(o4[n].z - f23.x, o4[n].w - f23.y);
    }
}

// ---------------------------------------------------------------------------
// LayerNorm + residual, fp32 src (node path)
// ---------------------------------------------------------------------------
__global__ void __launch_bounds__(256) ln_res_kernel(
    const float* __restrict__ src, const float* __restrict__ resid,
    const float* __restrict__ gamma, const float* __restrict__ beta,
    float* __restrict__ dst)
{
    const int row = blockIdx.x;
    const int t = threadIdx.x;
    const float4 v = *(const float4*)&src[(size_t)row * DIM + t * 4];

    float sum = v.x + v.y + v.z + v.w;
    float sq = v.x * v.x + v.y * v.y + v.z * v.z + v.w * v.w;
#pragma unroll
    for (int o = 16; o; o >>= 1) {
        sum += __shfl_xor_sync(0xFFFFFFFFu, sum, o);
        sq  += __shfl_xor_sync(0xFFFFFFFFu, sq, o);
    }
    __shared__ float ssum[8], ssq[8];
    const int w = t >> 5, l = t & 31;
    if (l == 0) { ssum[w] = sum; ssq[w] = sq; }
    __syncthreads();
    sum = 0.f; sq = 0.f;
#pragma unroll
    for (int i = 0; i < 8; i++) { sum += ssum[i]; sq += ssq[i]; }

    const float mu = sum * (1.f / DIM);
    const float var = sq * (1.f / DIM) - mu * mu;
    const float rstd = rsqrtf(var + 1e-5f);

    const float4 g = *(const float4*)&gamma[t * 4];
    const float4 b = *(const float4*)&beta[t * 4];
    const float4 rr = *(const float4*)&resid[(size_t)row * DIM + t * 4];
    float4 o;
    o.x = (v.x - mu) * rstd * g.x + b.x + rr.x;
    o.y = (v.y - mu) * rstd * g.y + b.y + rr.y;
    o.z = (v.z - mu) * rstd * g.z + b.z + rr.z;
    o.w = (v.w - mu) * rstd * g.w + b.w + rr.w;
    *(float4*)&dst[(size_t)row * DIM + t * 4] = o;
}

// ---------------------------------------------------------------------------
// LayerNorm + residual, fp16 src AND fp16 resid (edge path) -> fp32 out
// ---------------------------------------------------------------------------
__global__ void __launch_bounds__(256) ln_res_hh_kernel(
    const __half* __restrict__ src, const __half* __restrict__ resid,
    const float* __restrict__ gamma, const float* __restrict__ beta,
    float* __restrict__ dst)
{
    const int row = blockIdx.x;
    const int t = threadIdx.x;
    const size_t base = (size_t)row * DIM + t * 4;
    const __half2 h01 = *(const __half2*)&src[base];
    const __half2 h23 = *(const __half2*)&src[base + 2];
    const float2 f01 = __half22float2(h01);
    const float2 f23 = __half22float2(h23);
    float4 v = make_float4(f01.x, f01.y, f23.x, f23.y);

    float sum = v.x + v.y + v.z + v.w;
    float sq = v.x * v.x + v.y * v.y + v.z * v.z + v.w * v.w;
#pragma unroll
    for (int o = 16; o; o >>= 1) {
        sum += __shfl_xor_sync(0xFFFFFFFFu, sum, o);
        sq  += __shfl_xor_sync(0xFFFFFFFFu, sq, o);
    }
    __shared__ float ssum[8], ssq[8];
    const int w = t >> 5, l = t & 31;
    if (l == 0) { ssum[w] = sum; ssq[w] = sq; }
    __syncthreads();
    sum = 0.f; sq = 0.f;
#pragma unroll
    for (int i = 0; i < 8; i++) { sum += ssum[i]; sq += ssq[i]; }

    const float mu = sum * (1.f / DIM);
    const float var = sq * (1.f / DIM) - mu * mu;
    const float rstd = rsqrtf(var + 1e-5f);

    const float4 g = *(const float4*)&gamma[t * 4];
    const float4 b = *(const float4*)&beta[t * 4];
    const __half2 r01 = *(const __half2*)&resid[base];
    const __half2 r23 = *(const __half2*)&resid[base + 2];
    const float2 rf01 = __half22float2(r01);
    const float2 rf23 = __half22float2(r23);
    float4 o;
    o.x = (v.x - mu) * rstd * g.x + b.x + rf01.x;
    o.y = (v.y - mu) * rstd * g.y + b.y + rf01.y;
    o.z = (v.z - mu) * rstd * g.z + b.z + rf23.x;
    o.w = (v.w - mu) * rstd * g.w + b.w + rf23.y;
    *(float4*)&dst[base] = o;
}

// ---------------------------------------------------------------------------
// kernel_launch (single stream)
// ---------------------------------------------------------------------------
extern "C" void kernel_launch(void* const* d_in, const int* in_sizes, int n_in,
                              void* d_out, int out_size)
{
    const float* node       = (const float*)d_in[0];
    const float* edge       = (const float*)d_in[1];
    const float* w_query    = (const float*)d_in[2];
    const float* b_query    = (const float*)d_in[3];
    const float* w_edge     = (const float*)d_in[4];
    const float* b_edge     = (const float*)d_in[5];
    const float* w_to_q     = (const float*)d_in[6];
    const float* w_to_k     = (const float*)d_in[7];
    const float* proj_k     = (const float*)d_in[8];
    const float* w_out      = (const float*)d_in[9];
    const float* b_out      = (const float*)d_in[10];
    const float* gamma_node = (const float*)d_in[11];
    const float* beta_node  = (const float*)d_in[12];
    const float* gamma_edge = (const float*)d_in[13];
    const float* beta_edge  = (const float*)d_in[14];

    float* x_out = (float*)d_out;
    float* y_out = (float*)d_out + (size_t)N_NODES * DIM;

    __half *e16, *y16, *weT16, *nh16, *nl16, *wqT16, *wqkT16, *woT16;
    __half *xqh16, *xql16, *ah16, *al16;
    float *qkv, *kp, *xattn;
    cudaGetSymbolAddress((void**)&e16, g_e16);
    cudaGetSymbolAddress((void**)&y16, g_y16);
    cudaGetSymbolAddress((void**)&weT16, g_weT16);
    cudaGetSymbolAddress((void**)&nh16, g_nh16);
    cudaGetSymbolAddress((void**)&nl16, g_nl16);
    cudaGetSymbolAddress((void**)&wqT16, g_wqT16);
    cudaGetSymbolAddress((void**)&wqkT16, g_wqkT16);
    cudaGetSymbolAddress((void**)&woT16, g_woT16);
    cudaGetSymbolAddress((void**)&xqh16, g_xqh16);
    cudaGetSymbolAddress((void**)&xql16, g_xql16);
    cudaGetSymbolAddress((void**)&ah16, g_ah16);
    cudaGetSymbolAddress((void**)&al16, g_al16);
    cudaGetSymbolAddress((void**)&qkv, g_qkv);
    cudaGetSymbolAddress((void**)&kp, g_kproj);
    cudaGetSymbolAddress((void**)&xattn, g_xattn);

    static bool attr_set = false;
    if (!attr_set) {
        cudaFuncSetAttribute(gemm_f16n,
                             cudaFuncAttributeMaxDynamicSharedMemorySize, M_SM);
        cudaFuncSetAttribute(gemm_f16_sw,
                             cudaFuncAttributeMaxDynamicSharedMemorySize, E_SM);
        cudaFuncSetAttribute(attn_v3,
                             cudaFuncAttributeMaxDynamicSharedMemorySize, ATTN_SMEM);
        attr_set = true;
    }

    // 1. fused elementwise converts
    fused_conv_kernel<<<CONV_BLOCKS, 256>>>(
        (const float4*)edge, (__half2*)e16,
        (const float4*)node, (__half2*)nh16, (__half2*)nl16);
    // 2. fused weight prep (all fp16)
    fused_wprep_kernel<<<WPREP_BLOCKS, dim3(32, 8)>>>(
        w_query, w_to_q, w_to_k, w_out, w_edge,
        wqT16, wqkT16, woT16, weT16);
    // 3. node GEMM #1 (xq -> fp16 hi/lo)
    gemm_f16n<<<dim3(8, 32), 256, M_SM>>>(
        nh16, nl16, wqT16, b_query, nullptr, xqh16, xql16, DIM);
    // 4. edge GEMM -> fp16 intermediate (profiled slot)
    gemm_f16_sw<<<dim3(8, 256), 256, E_SM>>>(e16, weT16, b_edge, y16, DIM);
    // 5. edge LN (fp16 src + fp16 resid -> fp32 out)
    ln_res_hh_kernel<<<N_EDGES, 256>>>(y16, e16, gamma_edge, beta_edge, y_out);
    // 6. node GEMM #2 (qkv fp32)
    gemm_f16n<<<dim3(9, 32), 256, M_SM>>>(
        xqh16, xql16, wqkT16, nullptr, qkv, nullptr, nullptr, QKV_N);
    // 7-8. kproj + attention
    kproj_kernel<<<KPROJ, 128>>>(qkv + 1024, QKV_N, proj_k, kp);
    attn_v3<<<N_NODES / NPB, 256, ATTN_SMEM>>>(qkv, QKV_N, kp, ah16, al16);
    // 9. node GEMM #3 (x_attn fp32)
    gemm_f16n<<<dim3(8, 32), 256, M_SM>>>(
        ah16, al16, woT16, b_out, xattn, nullptr, nullptr, DIM);
    // 10. node LN
    ln_res_kernel<<<N_NODES, 256>>>(xattn, node, gamma_node, beta_node, x_out);
}